// round 12
// baseline (speedup 1.0000x reference)
#include <cuda_runtime.h>
#include <math.h>

// Fixed problem shapes
#define BB 4
#define NN 2048
#define FF 256
#define HH 512
#define EE 65536
#define ROWS (BB*NN)          // 8192
#define TOT  (ROWS*FF)        // 2097152

// ---------------- scratch (device globals; no cudaMalloc allowed) ----------
__device__ float g_kbuf[7 * TOT];
__device__ float g_ya[TOT];
__device__ float g_yb[TOT];
__device__ float g_yi[TOT];
__device__ float g_h1[ROWS * HH];
__device__ float g_h2[ROWS * HH];
__device__ float g_tmp[TOT];
__device__ float g_g1[TOT];
__device__ float g_dc[ROWS];
__device__ float g_ctx[BB * HH];
__device__ float g_ew[EE];
__device__ float g_val[EE];
__device__ float g_dis[NN];
__device__ float g_diag[NN];
__device__ int   g_deg[NN];
__device__ int   g_rowcnt[NN];
__device__ int   g_fill[NN];
__device__ int   g_rowptr[NN + 1];
__device__ int   g_colidx[EE];

// ---------------- graph / Laplacian build ----------------------------------

__global__ void init_graph_kernel(int* deg, int* rowcnt, int* fill) {
    int i = blockIdx.x * 256 + threadIdx.x;
    if (i < NN) { deg[i] = 1; rowcnt[i] = 0; fill[i] = 0; }  // deg=1: self loop
}

__global__ void edgew_kernel(const float* __restrict__ attr,
                             const float* __restrict__ w1, const float* __restrict__ b1,
                             const float* __restrict__ w2, const float* __restrict__ b2,
                             float* __restrict__ ew) {
    int e = blockIdx.x * 256 + threadIdx.x;
    if (e >= EE) return;
    float a = attr[e];
    float s = b2[0];
    #pragma unroll
    for (int j = 0; j < 32; j++) {
        float h = fmaxf(fmaf(a, w1[j], b1[j]), 0.f);
        s = fmaf(h, w2[j], s);
    }
    ew[e] = 1.f / (1.f + expf(-s));
}

__global__ void count_kernel(const int* __restrict__ ei, int* rowcnt, int* deg) {
    int e = blockIdx.x * 256 + threadIdx.x;
    if (e >= EE) return;
    atomicAdd(&rowcnt[ei[e]], 1);       // row
    atomicAdd(&deg[ei[EE + e]], 1);     // col (unweighted degree)
}

__global__ void disdiag_kernel(const int* __restrict__ deg, float* dis, float* diag) {
    int i = blockIdx.x * 256 + threadIdx.x;
    if (i >= NN) return;
    float d = rsqrtf((float)deg[i]);
    dis[i] = d;
    diag[i] = 1.f - d * d;   // L = I - adj; self-loop weight is dis[i]^2
}

// exclusive scan of 2048 counts -> rowptr (single block, 256 threads x 8)
__global__ void scan_kernel(const int* __restrict__ cnt, int* __restrict__ rowptr) {
    __shared__ int part[256];
    int t = threadIdx.x;
    int loc[8]; int s = 0;
    #pragma unroll
    for (int i = 0; i < 8; i++) { loc[i] = s; s += cnt[t * 8 + i]; }
    part[t] = s;
    __syncthreads();
    for (int off = 1; off < 256; off <<= 1) {
        int v = (t >= off) ? part[t - off] : 0;
        __syncthreads();
        part[t] += v;
        __syncthreads();
    }
    int base = t ? part[t - 1] : 0;
    #pragma unroll
    for (int i = 0; i < 8; i++) rowptr[t * 8 + i] = base + loc[i];
    if (t == 255) rowptr[NN] = part[255];
}

__global__ void scatter_kernel(const int* __restrict__ ei, const float* __restrict__ ew,
                               const float* __restrict__ dis, const int* __restrict__ rowptr,
                               int* fill, int* __restrict__ colidx, float* __restrict__ val) {
    int e = blockIdx.x * 256 + threadIdx.x;
    if (e >= EE) return;
    int r = ei[e], c = ei[EE + e];
    int pos = rowptr[r] + atomicAdd(&fill[r], 1);
    colidx[pos] = c;
    val[pos] = dis[r] * ew[e] * dis[c];
}

// ---------------- context projection (once per launch) ---------------------
__global__ void ctxproj_kernel(const float* __restrict__ context,
                               const float* __restrict__ w1, const float* __restrict__ b1,
                               float* __restrict__ out) {
    int b = blockIdx.x, n = threadIdx.x;  // 512 threads
    float s = b1[n];
    for (int k = 0; k < FF; k++)
        s = fmaf(context[b * FF + k], w1[(size_t)(FF + k) * HH + n], s);
    out[b * HH + n] = s;
}

// ---------------- SGEMM with packed fp32x2 FMA ------------------------------
// C[M,N] = A[M,K] @ B[K,N] (+ biases, opt relu)
// BM=128, BN=64, BK=32, 256 threads, 8x4 per thread.
// Shared tiles are K-CONTIGUOUS: As[row][k], Bs[col][k]. Even/odd k live in the
// lo/hi lanes of 64-bit packed registers; fma.rn.f32x2 accumulates both partial
// sums per issue slot (2x FFMA throughput), summed in the epilogue.
#define AS_STRIDE 36   // 36*4 = 144 B: 16B-aligned rows, rows spread across banks
#define BS_STRIDE 34   // 34*4 = 136 B: 8B-aligned, cols land on distinct bank pairs

__global__ __launch_bounds__(256, 2) void sgemm_kernel(
    const float* __restrict__ A, const float* __restrict__ B,
    float* __restrict__ C, int M, int N, int K, int ldb,
    const float* __restrict__ colBias,      // [N] or null
    const float* __restrict__ batchBias,    // [(row>>11)*N + col] or null
    int doRelu)
{
    __shared__ float As[128 * AS_STRIDE];
    __shared__ float Bs[64 * BS_STRIDE];
    int tid = threadIdx.x;
    int bn = blockIdx.x, bm = blockIdx.y;
    int tr = tid >> 4, tc = tid & 15;

    // A tile: 128 rows x 32 k; thread does 4 float4 rows
    int aRow = tid >> 3;          // 0..31 (+32*it)
    int aCol = (tid & 7) << 2;    // 0..28 step 4
    // B tile: 32 k x 64 cols; thread owns one col, 8 consecutive k
    int bCol = tid & 63;
    int bK0 = (tid >> 6) << 3;    // 0,8,16,24

    const float* Ab = A + (size_t)bm * 128 * K;
    const float* Bb = B + (size_t)bn * 64 + bCol;

    unsigned long long acc[8][4];
    #pragma unroll
    for (int i = 0; i < 8; i++)
        #pragma unroll
        for (int j = 0; j < 4; j++) acc[i][j] = 0ull;

    // prefetch registers
    float4 aReg[4];
    float  bReg[8];
    #pragma unroll
    for (int it = 0; it < 4; it++)
        aReg[it] = *(const float4*)(Ab + (size_t)(aRow + 32 * it) * K + aCol);
    #pragma unroll
    for (int t = 0; t < 8; t++)
        bReg[t] = Bb[(size_t)(bK0 + t) * ldb];

    const float* Ar = As + tr * 8 * AS_STRIDE;
    const float* Br = Bs + tc * 4 * BS_STRIDE;

    for (int k0 = 0; k0 < K; k0 += 32) {
        // regs -> smem
        #pragma unroll
        for (int it = 0; it < 4; it++)
            *(float4*)(As + (aRow + 32 * it) * AS_STRIDE + aCol) = aReg[it];
        #pragma unroll
        for (int t = 0; t < 4; t++)
            *(float2*)(Bs + bCol * BS_STRIDE + bK0 + 2 * t) =
                make_float2(bReg[2 * t], bReg[2 * t + 1]);
        __syncthreads();

        // prefetch next tile (overlaps with compute)
        if (k0 + 32 < K) {
            #pragma unroll
            for (int it = 0; it < 4; it++)
                aReg[it] = *(const float4*)(Ab + (size_t)(aRow + 32 * it) * K + k0 + 32 + aCol);
            #pragma unroll
            for (int t = 0; t < 8; t++)
                bReg[t] = Bb[(size_t)(k0 + 32 + bK0 + t) * ldb];
        }

        // compute: 16 k-pairs, packed even/odd k in lo/hi lanes
        #pragma unroll
        for (int kp = 0; kp < 16; kp++) {
            unsigned long long ra[8], rb[4];
            #pragma unroll
            for (int i = 0; i < 8; i++)
                ra[i] = *(const unsigned long long*)(Ar + i * AS_STRIDE + 2 * kp);
            #pragma unroll
            for (int j = 0; j < 4; j++)
                rb[j] = *(const unsigned long long*)(Br + j * BS_STRIDE + 2 * kp);
            #pragma unroll
            for (int i = 0; i < 8; i++)
                #pragma unroll
                for (int j = 0; j < 4; j++)
                    asm("fma.rn.f32x2 %0, %1, %2, %0;"
                        : "+l"(acc[i][j]) : "l"(ra[i]), "l"(rb[j]));
        }
        __syncthreads();
    }

    int col = bn * 64 + tc * 4;
    float4 cb = make_float4(0.f, 0.f, 0.f, 0.f);
    if (colBias) cb = *(const float4*)(colBias + col);
    #pragma unroll
    for (int i = 0; i < 8; i++) {
        int row = bm * 128 + tr * 8 + i;
        float bx = cb.x, by = cb.y, bz = cb.z, bw = cb.w;
        if (batchBias) {
            float4 b2 = *(const float4*)(batchBias + (size_t)(row >> 11) * N + col);
            bx += b2.x; by += b2.y; bz += b2.z; bw += b2.w;
        }
        float2 s0 = *reinterpret_cast<float2*>(&acc[i][0]);
        float2 s1 = *reinterpret_cast<float2*>(&acc[i][1]);
        float2 s2 = *reinterpret_cast<float2*>(&acc[i][2]);
        float2 s3 = *reinterpret_cast<float2*>(&acc[i][3]);
        float4 o;
        o.x = (s0.x + s0.y) + bx; o.y = (s1.x + s1.y) + by;
        o.z = (s2.x + s2.y) + bz; o.w = (s3.x + s3.y) + bw;
        if (doRelu) {
            o.x = fmaxf(o.x, 0.f); o.y = fmaxf(o.y, 0.f);
            o.z = fmaxf(o.z, 0.f); o.w = fmaxf(o.w, 0.f);
        }
        *(float4*)(C + (size_t)row * N + col) = o;
    }
}

// ---------------- LayerNorm(width=512) + ReLU, in-place, two-pass ----------
__global__ __launch_bounds__(256) void ln_relu_kernel(float* __restrict__ x,
                                                      const float* __restrict__ g,
                                                      const float* __restrict__ b) {
    int row = blockIdx.x;
    float* xr = x + (size_t)row * HH;
    int t = threadIdx.x;
    float2 v = ((float2*)xr)[t];
    __shared__ float ws[8];
    __shared__ float mu_s, inv_s;
    int lane = t & 31, w = t >> 5;

    float s = v.x + v.y;
    #pragma unroll
    for (int o = 16; o; o >>= 1) s += __shfl_xor_sync(0xffffffffu, s, o);
    if (!lane) ws[w] = s;
    __syncthreads();
    if (t == 0) {
        float tot = 0.f;
        #pragma unroll
        for (int i = 0; i < 8; i++) tot += ws[i];
        mu_s = tot * (1.f / HH);
    }
    __syncthreads();
    float mu = mu_s;
    float dx = v.x - mu, dy = v.y - mu;
    s = dx * dx + dy * dy;
    #pragma unroll
    for (int o = 16; o; o >>= 1) s += __shfl_xor_sync(0xffffffffu, s, o);
    if (!lane) ws[w] = s;
    __syncthreads();
    if (t == 0) {
        float tot = 0.f;
        #pragma unroll
        for (int i = 0; i < 8; i++) tot += ws[i];
        inv_s = rsqrtf(tot * (1.f / HH) + 1e-5f);
    }
    __syncthreads();
    float inv = inv_s;
    float2 gv = ((const float2*)g)[t];
    float2 bv = ((const float2*)b)[t];
    float2 o;
    o.x = fmaxf(fmaf(dx * inv, gv.x, bv.x), 0.f);
    o.y = fmaxf(fmaf(dy * inv, gv.y, bv.y), 0.f);
    ((float2*)xr)[t] = o;
}

// ---------------- dcoef: sigmoid(row-dot) ----------------------------------
__global__ __launch_bounds__(256) void dcoef_kernel(const float* __restrict__ g1,
                                                    const float* __restrict__ w2,
                                                    const float* __restrict__ b2,
                                                    float* __restrict__ dc) {
    int lane = threadIdx.x & 31, w = threadIdx.x >> 5;
    int row = blockIdx.x * 8 + w;
    const float* r = g1 + (size_t)row * FF;
    float s = 0.f;
    #pragma unroll
    for (int j = 0; j < FF / 32; j++)
        s = fmaf(r[lane + j * 32], w2[lane + j * 32], s);
    #pragma unroll
    for (int o = 16; o; o >>= 1) s += __shfl_xor_sync(0xffffffffu, s, o);
    if (!lane) dc[row] = 1.f / (1.f + expf(-(s + b2[0])));
}

// ---------------- fused SpMM diffusion + combine ----------------------------
__global__ __launch_bounds__(256) void spmm_kernel(
    const float* __restrict__ y, const float* __restrict__ temporal,
    const float* __restrict__ dc, const int* __restrict__ rowptr,
    const int* __restrict__ colidx, const float* __restrict__ val,
    const float* __restrict__ diag, float* __restrict__ kout)
{
    int i = blockIdx.x, b = blockIdx.y, f = threadIdx.x;
    const float* yb = y + (size_t)b * NN * FF;
    float acc = diag[i] * yb[(size_t)i * FF + f];
    int e1 = rowptr[i + 1];
    for (int e = rowptr[i]; e < e1; ++e)
        acc = fmaf(-val[e], yb[(size_t)colidx[e] * FF + f], acc);
    size_t o = ((size_t)b * NN + i) * FF + f;
    kout[o] = temporal[o] - dc[b * NN + i] * acc;
}

// ---------------- stage combine: out = y + sum c_j * k_j -------------------
__global__ __launch_bounds__(256) void axpy_kernel(
    float4* __restrict__ out, const float4* __restrict__ y,
    const float4* k0, const float4* k1, const float4* k2,
    const float4* k3, const float4* k4, const float4* k5,
    float c0, float c1, float c2, float c3, float c4, float c5)
{
    int i = blockIdx.x * 256 + threadIdx.x;  // grid = TOT/4/256
    float4 v = y[i];
#define ACCK(kk, cc) if (kk) { float4 a = kk[i]; \
    v.x = fmaf(cc, a.x, v.x); v.y = fmaf(cc, a.y, v.y); \
    v.z = fmaf(cc, a.z, v.z); v.w = fmaf(cc, a.w, v.w); }
    ACCK(k0, c0) ACCK(k1, c1) ACCK(k2, c2) ACCK(k3, c3) ACCK(k4, c4) ACCK(k5, c5)
#undef ACCK
    out[i] = v;
}

__global__ void copy_kernel(float4* __restrict__ dst, const float4* __restrict__ src) {
    int i = blockIdx.x * 256 + threadIdx.x;
    dst[i] = src[i];
}

// ---------------- host orchestration ----------------------------------------

struct Wts {
    const float *td_w1, *td_b2, *ln1_g, *ln1_b, *td_w2, *ln2_g, *ln2_b,
                *td_w3, *td_b3, *df_w1, *df_b1, *df_w2, *df_b2;
    float *h1, *h2, *tmp, *g1, *dc, *ctx;
    const int *rowptr, *colidx;
    const float *val, *diag;
};

static void feval(const float* y, float* kout, const Wts& w) {
    dim3 gBig(HH / 64, ROWS / 128);     // (8, 64)
    dim3 gSmall(FF / 64, ROWS / 128);   // (4, 64)
    sgemm_kernel<<<gBig, 256>>>(y, w.td_w1, w.h1, ROWS, HH, FF, HH, nullptr, w.ctx, 0);
    ln_relu_kernel<<<ROWS, 256>>>(w.h1, w.ln1_g, w.ln1_b);
    sgemm_kernel<<<gBig, 256>>>(w.h1, w.td_w2, w.h2, ROWS, HH, HH, HH, w.td_b2, nullptr, 0);
    ln_relu_kernel<<<ROWS, 256>>>(w.h2, w.ln2_g, w.ln2_b);
    sgemm_kernel<<<gSmall, 256>>>(w.h2, w.td_w3, w.tmp, ROWS, FF, HH, FF, w.td_b3, nullptr, 0);
    sgemm_kernel<<<gSmall, 256>>>(y, w.df_w1, w.g1, ROWS, FF, FF, FF, w.df_b1, nullptr, 1);
    dcoef_kernel<<<ROWS / 8, 256>>>(w.g1, w.df_w2, w.df_b2, w.dc);
    spmm_kernel<<<dim3(NN, BB), 256>>>(y, w.tmp, w.dc, w.rowptr, w.colidx, w.val, w.diag, kout);
}

extern "C" void kernel_launch(void* const* d_in, const int* in_sizes, int n_in,
                              void* d_out, int out_size)
{
    const float* state     = (const float*)d_in[0];
    const float* context   = (const float*)d_in[1];
    const float* edge_attr = (const float*)d_in[2];
    const int*   edge_idx  = (const int*)  d_in[3];
    const float* ew_w1 = (const float*)d_in[4];
    const float* ew_b1 = (const float*)d_in[5];
    const float* ew_w2 = (const float*)d_in[6];
    const float* ew_b2 = (const float*)d_in[7];
    const float* td_w1 = (const float*)d_in[8];
    const float* td_b1 = (const float*)d_in[9];
    const float* ln1_g = (const float*)d_in[10];
    const float* ln1_b = (const float*)d_in[11];
    const float* td_w2 = (const float*)d_in[12];
    const float* td_b2 = (const float*)d_in[13];
    const float* ln2_g = (const float*)d_in[14];
    const float* ln2_b = (const float*)d_in[15];
    const float* td_w3 = (const float*)d_in[16];
    const float* td_b3 = (const float*)d_in[17];
    const float* df_w1 = (const float*)d_in[18];
    const float* df_b1 = (const float*)d_in[19];
    const float* df_w2 = (const float*)d_in[20];
    const float* df_b2 = (const float*)d_in[21];

    float *kbuf, *ya, *yb, *yi, *h1, *h2, *tmp, *g1, *dc, *ctx;
    float *ew, *val, *dis, *diag;
    int *deg, *rowcnt, *fill, *rowptr, *colidx;
    cudaGetSymbolAddress((void**)&kbuf,  g_kbuf);
    cudaGetSymbolAddress((void**)&ya,    g_ya);
    cudaGetSymbolAddress((void**)&yb,    g_yb);
    cudaGetSymbolAddress((void**)&yi,    g_yi);
    cudaGetSymbolAddress((void**)&h1,    g_h1);
    cudaGetSymbolAddress((void**)&h2,    g_h2);
    cudaGetSymbolAddress((void**)&tmp,   g_tmp);
    cudaGetSymbolAddress((void**)&g1,    g_g1);
    cudaGetSymbolAddress((void**)&dc,    g_dc);
    cudaGetSymbolAddress((void**)&ctx,   g_ctx);
    cudaGetSymbolAddress((void**)&ew,    g_ew);
    cudaGetSymbolAddress((void**)&val,   g_val);
    cudaGetSymbolAddress((void**)&dis,   g_dis);
    cudaGetSymbolAddress((void**)&diag,  g_diag);
    cudaGetSymbolAddress((void**)&deg,   g_deg);
    cudaGetSymbolAddress((void**)&rowcnt,g_rowcnt);
    cudaGetSymbolAddress((void**)&fill,  g_fill);
    cudaGetSymbolAddress((void**)&rowptr,g_rowptr);
    cudaGetSymbolAddress((void**)&colidx,g_colidx);

    // ---- 1. Build normalized Laplacian as CSR (once per launch) ----
    init_graph_kernel<<<NN / 256, 256>>>(deg, rowcnt, fill);
    edgew_kernel<<<EE / 256, 256>>>(edge_attr, ew_w1, ew_b1, ew_w2, ew_b2, ew);
    count_kernel<<<EE / 256, 256>>>(edge_idx, rowcnt, deg);
    disdiag_kernel<<<NN / 256, 256>>>(deg, dis, diag);
    scan_kernel<<<1, 256>>>(rowcnt, rowptr);
    scatter_kernel<<<EE / 256, 256>>>(edge_idx, ew, dis, rowptr, fill, colidx, val);

    // ---- 2. Constant context projection (absorbs td_b1) ----
    ctxproj_kernel<<<BB, HH>>>(context, td_w1, td_b1, ctx);

    // ---- 3. y0 = state ----
    copy_kernel<<<TOT / 4 / 256, 256>>>((float4*)ya, (const float4*)state);

    Wts w;
    w.td_w1 = td_w1; w.td_b2 = td_b2; w.ln1_g = ln1_g; w.ln1_b = ln1_b;
    w.td_w2 = td_w2; w.ln2_g = ln2_g; w.ln2_b = ln2_b;
    w.td_w3 = td_w3; w.td_b3 = td_b3;
    w.df_w1 = df_w1; w.df_b1 = df_b1; w.df_w2 = df_w2; w.df_b2 = df_b2;
    w.h1 = h1; w.h2 = h2; w.tmp = tmp; w.g1 = g1; w.dc = dc; w.ctx = ctx;
    w.rowptr = rowptr; w.colidx = colidx; w.val = val; w.diag = diag;

    // ---- 4. dopri5, 4 fixed steps, FSAL reuse ----
    const double dt = 0.25;
    const double A2[1] = {1.0 / 5};
    const double A3[2] = {3.0 / 40, 9.0 / 40};
    const double A4[3] = {44.0 / 45, -56.0 / 15, 32.0 / 9};
    const double A5[4] = {19372.0 / 6561, -25360.0 / 2187, 64448.0 / 6561, -212.0 / 729};
    const double A6[5] = {9017.0 / 3168, -355.0 / 33, 46732.0 / 5247, 49.0 / 176, -5103.0 / 18656};
    const double BW[6] = {35.0 / 384, 0.0, 500.0 / 1113, 125.0 / 192, -2187.0 / 6784, 11.0 / 84};
    const double* Arows[5] = {A2, A3, A4, A5, A6};

    float* kp[7];
    for (int i = 0; i < 7; i++) kp[i] = kbuf + (size_t)i * TOT;

    float* ycur = ya;
    float* yoth = yb;
    const int nAx = TOT / 4 / 256;

    for (int s = 0; s < 4; ++s) {
        if (s == 0) feval(ycur, kp[0], w);   // else FSAL: kp[0] = prev step's k7

        for (int i = 1; i <= 5; ++i) {
            const double* a = Arows[i - 1];
            const float4* ks[6] = {nullptr, nullptr, nullptr, nullptr, nullptr, nullptr};
            float cs[6] = {0, 0, 0, 0, 0, 0};
            for (int j = 0; j < i; j++) { ks[j] = (const float4*)kp[j]; cs[j] = (float)(dt * a[j]); }
            axpy_kernel<<<nAx, 256>>>((float4*)yi, (const float4*)ycur,
                                      ks[0], ks[1], ks[2], ks[3], ks[4], ks[5],
                                      cs[0], cs[1], cs[2], cs[3], cs[4], cs[5]);
            feval(yi, kp[i], w);
        }

        float* ynext = (s == 3) ? (float*)d_out : yoth;
        axpy_kernel<<<nAx, 256>>>((float4*)ynext, (const float4*)ycur,
                                  (const float4*)kp[0], nullptr,
                                  (const float4*)kp[2], (const float4*)kp[3],
                                  (const float4*)kp[4], (const float4*)kp[5],
                                  (float)(dt * BW[0]), 0.f,
                                  (float)(dt * BW[2]), (float)(dt * BW[3]),
                                  (float)(dt * BW[4]), (float)(dt * BW[5]));

        if (s < 3) {
            // FSAL: k7 = f(ynew) becomes next step's k1
            feval(ynext, kp[6], w);
            float* t = kp[0]; kp[0] = kp[6]; kp[6] = t;
            yoth = ycur;
            ycur = ynext;
        }
    }
}

// round 13
// speedup vs baseline: 1.0630x; 1.0630x over previous
#include <cuda_runtime.h>
#include <math.h>

// Fixed problem shapes
#define BB 4
#define NN 2048
#define FF 256
#define HH 512
#define EE 65536
#define ROWS (BB*NN)          // 8192
#define TOT  (ROWS*FF)        // 2097152

// ---------------- scratch (device globals; no cudaMalloc allowed) ----------
__device__ float g_kbuf[7 * TOT];
__device__ float g_ya[TOT];
__device__ float g_yb[TOT];
__device__ float g_yi[TOT];
__device__ float g_h1[ROWS * HH];
__device__ float g_h2[ROWS * HH];
__device__ float g_tmp[TOT];
__device__ float g_g1[TOT];
__device__ float g_dc[ROWS];
__device__ float g_ctx[BB * HH];
__device__ float g_ew[EE];
__device__ float g_val[EE];
__device__ float g_dis[NN];
__device__ float g_diag[NN];
__device__ int   g_deg[NN];
__device__ int   g_rowcnt[NN];
__device__ int   g_fill[NN];
__device__ int   g_rowptr[NN + 1];
__device__ int   g_colidx[EE];

// ---------------- graph / Laplacian build ----------------------------------

__global__ void init_graph_kernel(int* deg, int* rowcnt, int* fill) {
    int i = blockIdx.x * 256 + threadIdx.x;
    if (i < NN) { deg[i] = 1; rowcnt[i] = 0; fill[i] = 0; }  // deg=1: self loop
}

__global__ void edgew_kernel(const float* __restrict__ attr,
                             const float* __restrict__ w1, const float* __restrict__ b1,
                             const float* __restrict__ w2, const float* __restrict__ b2,
                             float* __restrict__ ew) {
    int e = blockIdx.x * 256 + threadIdx.x;
    if (e >= EE) return;
    float a = attr[e];
    float s = b2[0];
    #pragma unroll
    for (int j = 0; j < 32; j++) {
        float h = fmaxf(fmaf(a, w1[j], b1[j]), 0.f);
        s = fmaf(h, w2[j], s);
    }
    ew[e] = 1.f / (1.f + expf(-s));
}

__global__ void count_kernel(const int* __restrict__ ei, int* rowcnt, int* deg) {
    int e = blockIdx.x * 256 + threadIdx.x;
    if (e >= EE) return;
    atomicAdd(&rowcnt[ei[e]], 1);       // row
    atomicAdd(&deg[ei[EE + e]], 1);     // col (unweighted degree)
}

__global__ void disdiag_kernel(const int* __restrict__ deg, float* dis, float* diag) {
    int i = blockIdx.x * 256 + threadIdx.x;
    if (i >= NN) return;
    float d = rsqrtf((float)deg[i]);
    dis[i] = d;
    diag[i] = 1.f - d * d;   // L = I - adj; self-loop weight is dis[i]^2
}

// exclusive scan of 2048 counts -> rowptr (single block, 256 threads x 8)
__global__ void scan_kernel(const int* __restrict__ cnt, int* __restrict__ rowptr) {
    __shared__ int part[256];
    int t = threadIdx.x;
    int loc[8]; int s = 0;
    #pragma unroll
    for (int i = 0; i < 8; i++) { loc[i] = s; s += cnt[t * 8 + i]; }
    part[t] = s;
    __syncthreads();
    for (int off = 1; off < 256; off <<= 1) {
        int v = (t >= off) ? part[t - off] : 0;
        __syncthreads();
        part[t] += v;
        __syncthreads();
    }
    int base = t ? part[t - 1] : 0;
    #pragma unroll
    for (int i = 0; i < 8; i++) rowptr[t * 8 + i] = base + loc[i];
    if (t == 255) rowptr[NN] = part[255];
}

__global__ void scatter_kernel(const int* __restrict__ ei, const float* __restrict__ ew,
                               const float* __restrict__ dis, const int* __restrict__ rowptr,
                               int* fill, int* __restrict__ colidx, float* __restrict__ val) {
    int e = blockIdx.x * 256 + threadIdx.x;
    if (e >= EE) return;
    int r = ei[e], c = ei[EE + e];
    int pos = rowptr[r] + atomicAdd(&fill[r], 1);
    colidx[pos] = c;
    val[pos] = dis[r] * ew[e] * dis[c];
}

// ---------------- context projection (once per launch) ---------------------
__global__ void ctxproj_kernel(const float* __restrict__ context,
                               const float* __restrict__ w1, const float* __restrict__ b1,
                               float* __restrict__ out) {
    int b = blockIdx.x, n = threadIdx.x;  // 512 threads
    float s = b1[n];
    for (int k = 0; k < FF; k++)
        s = fmaf(context[b * FF + k], w1[(size_t)(FF + k) * HH + n], s);
    out[b * HH + n] = s;
}

// ---------------- SGEMM, packed fp32x2, K-paired accumulators ---------------
// C[M,N] = A[M,K] @ B[K,N] (+ biases, opt relu)
// BM=128, BN=64, BK=32 (16 k-pairs), 256 threads, 8 rows x 4 cols per thread.
// acc lanes: lo = even-k partial sum, hi = odd-k partial sum; summed at end.
// A tile: float2 As2[kp][row]  (row-contiguous; ra loads are warp-broadcast)
// B tile: float  Bsf[col][k], stride 34; thread cols at stride 16 ->
//         rb LDS.64 lane bank step = 2 -> conflict-free.
#define AS2_STRIDE 130   // float2 units per kp-row (128 + pad)
#define BSF_STRIDE 34    // floats per col (32 + pad)

__global__ __launch_bounds__(256, 2) void sgemm_kernel(
    const float* __restrict__ A, const float* __restrict__ B,
    float* __restrict__ C, int M, int N, int K, int ldb,
    const float* __restrict__ colBias,      // [N] or null
    const float* __restrict__ batchBias,    // [(row>>11)*N + col] or null
    int doRelu)
{
    __shared__ __align__(16) float2 As2[16 * AS2_STRIDE];
    __shared__ float Bsf[64 * BSF_STRIDE];
    int tid = threadIdx.x;
    int bn = blockIdx.x, bm = blockIdx.y;
    int tr = tid >> 4;            // 0..15 -> rows tr*8 .. tr*8+7
    int tc = tid & 15;            // cols tc + 16j, j = 0..3

    // A staging: 128 rows x 32 k, float4 per row chunk
    int aRow = tid >> 3;          // 0..31 (+32*it)
    int aCol4 = (tid & 7) << 2;   // k offset 0..28 step 4
    // B staging: 32 k x 64 cols
    int bRow = tid >> 4;          // 0..15 (+16*it)
    int bCol = (tid & 15) << 2;   // 0..60 step 4

    const float* Ab = A + (size_t)bm * 128 * K;
    const float* Bb = B + (size_t)bn * 64;

    unsigned long long acc[8][4];
    #pragma unroll
    for (int i = 0; i < 8; i++)
        #pragma unroll
        for (int j = 0; j < 4; j++) acc[i][j] = 0ull;

    const float2* Arp = As2 + tr * 8;
    const float*  Brp = Bsf + tc * BSF_STRIDE;

    for (int k0 = 0; k0 < K; k0 += 32) {
        // A -> smem: float4 of 4 consecutive k = 2 k-pairs
        #pragma unroll
        for (int it = 0; it < 4; ++it) {
            int r = aRow + 32 * it;
            float4 v = *(const float4*)(Ab + (size_t)r * K + k0 + aCol4);
            int kp = aCol4 >> 1;   // 2c
            As2[(kp    ) * AS2_STRIDE + r] = make_float2(v.x, v.y);
            As2[(kp + 1) * AS2_STRIDE + r] = make_float2(v.z, v.w);
        }
        // B -> smem: coalesced row load, scattered col-major store
        #pragma unroll
        for (int it = 0; it < 2; ++it) {
            int r = bRow + 16 * it;
            float4 v = *(const float4*)(Bb + (size_t)(k0 + r) * ldb + bCol);
            Bsf[(bCol + 0) * BSF_STRIDE + r] = v.x;
            Bsf[(bCol + 1) * BSF_STRIDE + r] = v.y;
            Bsf[(bCol + 2) * BSF_STRIDE + r] = v.z;
            Bsf[(bCol + 3) * BSF_STRIDE + r] = v.w;
        }
        __syncthreads();

        #pragma unroll
        for (int kp = 0; kp < 16; kp++) {
            unsigned long long ra[8], rb[4];
            #pragma unroll
            for (int q = 0; q < 4; q++) {
                ulonglong2 t = *(const ulonglong2*)(Arp + kp * AS2_STRIDE + 2 * q);
                ra[2 * q] = t.x; ra[2 * q + 1] = t.y;
            }
            #pragma unroll
            for (int j = 0; j < 4; j++)
                rb[j] = *(const unsigned long long*)(Brp + j * 16 * BSF_STRIDE + 2 * kp);
            #pragma unroll
            for (int i = 0; i < 8; i++)
                #pragma unroll
                for (int j = 0; j < 4; j++)
                    asm("fma.rn.f32x2 %0, %1, %2, %0;"
                        : "+l"(acc[i][j]) : "l"(ra[i]), "l"(rb[j]));
        }
        __syncthreads();
    }

    // epilogue: sum even/odd-k partials, add biases, store scalars
    #pragma unroll
    for (int i = 0; i < 8; i++) {
        int row = bm * 128 + tr * 8 + i;
        float* Cr = C + (size_t)row * N + bn * 64;
        const float* bbr = batchBias ? batchBias + (size_t)(row >> 11) * N + bn * 64 : nullptr;
        #pragma unroll
        for (int j = 0; j < 4; j++) {
            int col = tc + 16 * j;
            float2 p = *reinterpret_cast<float2*>(&acc[i][j]);
            float v = p.x + p.y;
            if (colBias) v += colBias[bn * 64 + col];
            if (bbr) v += bbr[col];
            if (doRelu) v = fmaxf(v, 0.f);
            Cr[col] = v;
        }
    }
}

// ---------------- LayerNorm(width=512) + ReLU, in-place, two-pass ----------
__global__ __launch_bounds__(256) void ln_relu_kernel(float* __restrict__ x,
                                                      const float* __restrict__ g,
                                                      const float* __restrict__ b) {
    int row = blockIdx.x;
    float* xr = x + (size_t)row * HH;
    int t = threadIdx.x;
    float2 v = ((float2*)xr)[t];
    __shared__ float ws[8];
    __shared__ float mu_s, inv_s;
    int lane = t & 31, w = t >> 5;

    float s = v.x + v.y;
    #pragma unroll
    for (int o = 16; o; o >>= 1) s += __shfl_xor_sync(0xffffffffu, s, o);
    if (!lane) ws[w] = s;
    __syncthreads();
    if (t == 0) {
        float tot = 0.f;
        #pragma unroll
        for (int i = 0; i < 8; i++) tot += ws[i];
        mu_s = tot * (1.f / HH);
    }
    __syncthreads();
    float mu = mu_s;
    float dx = v.x - mu, dy = v.y - mu;
    s = dx * dx + dy * dy;
    #pragma unroll
    for (int o = 16; o; o >>= 1) s += __shfl_xor_sync(0xffffffffu, s, o);
    if (!lane) ws[w] = s;
    __syncthreads();
    if (t == 0) {
        float tot = 0.f;
        #pragma unroll
        for (int i = 0; i < 8; i++) tot += ws[i];
        inv_s = rsqrtf(tot * (1.f / HH) + 1e-5f);
    }
    __syncthreads();
    float inv = inv_s;
    float2 gv = ((const float2*)g)[t];
    float2 bv = ((const float2*)b)[t];
    float2 o;
    o.x = fmaxf(fmaf(dx * inv, gv.x, bv.x), 0.f);
    o.y = fmaxf(fmaf(dy * inv, gv.y, bv.y), 0.f);
    ((float2*)xr)[t] = o;
}

// ---------------- dcoef: sigmoid(row-dot) ----------------------------------
__global__ __launch_bounds__(256) void dcoef_kernel(const float* __restrict__ g1,
                                                    const float* __restrict__ w2,
                                                    const float* __restrict__ b2,
                                                    float* __restrict__ dc) {
    int lane = threadIdx.x & 31, w = threadIdx.x >> 5;
    int row = blockIdx.x * 8 + w;
    const float* r = g1 + (size_t)row * FF;
    float s = 0.f;
    #pragma unroll
    for (int j = 0; j < FF / 32; j++)
        s = fmaf(r[lane + j * 32], w2[lane + j * 32], s);
    #pragma unroll
    for (int o = 16; o; o >>= 1) s += __shfl_xor_sync(0xffffffffu, s, o);
    if (!lane) dc[row] = 1.f / (1.f + expf(-(s + b2[0])));
}

// ---------------- fused SpMM diffusion + combine ----------------------------
__global__ __launch_bounds__(256) void spmm_kernel(
    const float* __restrict__ y, const float* __restrict__ temporal,
    const float* __restrict__ dc, const int* __restrict__ rowptr,
    const int* __restrict__ colidx, const float* __restrict__ val,
    const float* __restrict__ diag, float* __restrict__ kout)
{
    int i = blockIdx.x, b = blockIdx.y, f = threadIdx.x;
    const float* yb = y + (size_t)b * NN * FF;
    float acc = diag[i] * yb[(size_t)i * FF + f];
    int e1 = rowptr[i + 1];
    for (int e = rowptr[i]; e < e1; ++e)
        acc = fmaf(-val[e], yb[(size_t)colidx[e] * FF + f], acc);
    size_t o = ((size_t)b * NN + i) * FF + f;
    kout[o] = temporal[o] - dc[b * NN + i] * acc;
}

// ---------------- stage combine: out = y + sum c_j * k_j -------------------
__global__ __launch_bounds__(256) void axpy_kernel(
    float4* __restrict__ out, const float4* __restrict__ y,
    const float4* k0, const float4* k1, const float4* k2,
    const float4* k3, const float4* k4, const float4* k5,
    float c0, float c1, float c2, float c3, float c4, float c5)
{
    int i = blockIdx.x * 256 + threadIdx.x;  // grid = TOT/4/256
    float4 v = y[i];
#define ACCK(kk, cc) if (kk) { float4 a = kk[i]; \
    v.x = fmaf(cc, a.x, v.x); v.y = fmaf(cc, a.y, v.y); \
    v.z = fmaf(cc, a.z, v.z); v.w = fmaf(cc, a.w, v.w); }
    ACCK(k0, c0) ACCK(k1, c1) ACCK(k2, c2) ACCK(k3, c3) ACCK(k4, c4) ACCK(k5, c5)
#undef ACCK
    out[i] = v;
}

__global__ void copy_kernel(float4* __restrict__ dst, const float4* __restrict__ src) {
    int i = blockIdx.x * 256 + threadIdx.x;
    dst[i] = src[i];
}

// ---------------- host orchestration ----------------------------------------

struct Wts {
    const float *td_w1, *td_b2, *ln1_g, *ln1_b, *td_w2, *ln2_g, *ln2_b,
                *td_w3, *td_b3, *df_w1, *df_b1, *df_w2, *df_b2;
    float *h1, *h2, *tmp, *g1, *dc, *ctx;
    const int *rowptr, *colidx;
    const float *val, *diag;
};

static void feval(const float* y, float* kout, const Wts& w) {
    dim3 gBig(HH / 64, ROWS / 128);     // (8, 64)
    dim3 gSmall(FF / 64, ROWS / 128);   // (4, 64)
    sgemm_kernel<<<gBig, 256>>>(y, w.td_w1, w.h1, ROWS, HH, FF, HH, nullptr, w.ctx, 0);
    ln_relu_kernel<<<ROWS, 256>>>(w.h1, w.ln1_g, w.ln1_b);
    sgemm_kernel<<<gBig, 256>>>(w.h1, w.td_w2, w.h2, ROWS, HH, HH, HH, w.td_b2, nullptr, 0);
    ln_relu_kernel<<<ROWS, 256>>>(w.h2, w.ln2_g, w.ln2_b);
    sgemm_kernel<<<gSmall, 256>>>(w.h2, w.td_w3, w.tmp, ROWS, FF, HH, FF, w.td_b3, nullptr, 0);
    sgemm_kernel<<<gSmall, 256>>>(y, w.df_w1, w.g1, ROWS, FF, FF, FF, w.df_b1, nullptr, 1);
    dcoef_kernel<<<ROWS / 8, 256>>>(w.g1, w.df_w2, w.df_b2, w.dc);
    spmm_kernel<<<dim3(NN, BB), 256>>>(y, w.tmp, w.dc, w.rowptr, w.colidx, w.val, w.diag, kout);
}

extern "C" void kernel_launch(void* const* d_in, const int* in_sizes, int n_in,
                              void* d_out, int out_size)
{
    const float* state     = (const float*)d_in[0];
    const float* context   = (const float*)d_in[1];
    const float* edge_attr = (const float*)d_in[2];
    const int*   edge_idx  = (const int*)  d_in[3];
    const float* ew_w1 = (const float*)d_in[4];
    const float* ew_b1 = (const float*)d_in[5];
    const float* ew_w2 = (const float*)d_in[6];
    const float* ew_b2 = (const float*)d_in[7];
    const float* td_w1 = (const float*)d_in[8];
    const float* td_b1 = (const float*)d_in[9];
    const float* ln1_g = (const float*)d_in[10];
    const float* ln1_b = (const float*)d_in[11];
    const float* td_w2 = (const float*)d_in[12];
    const float* td_b2 = (const float*)d_in[13];
    const float* ln2_g = (const float*)d_in[14];
    const float* ln2_b = (const float*)d_in[15];
    const float* td_w3 = (const float*)d_in[16];
    const float* td_b3 = (const float*)d_in[17];
    const float* df_w1 = (const float*)d_in[18];
    const float* df_b1 = (const float*)d_in[19];
    const float* df_w2 = (const float*)d_in[20];
    const float* df_b2 = (const float*)d_in[21];

    float *kbuf, *ya, *yb, *yi, *h1, *h2, *tmp, *g1, *dc, *ctx;
    float *ew, *val, *dis, *diag;
    int *deg, *rowcnt, *fill, *rowptr, *colidx;
    cudaGetSymbolAddress((void**)&kbuf,  g_kbuf);
    cudaGetSymbolAddress((void**)&ya,    g_ya);
    cudaGetSymbolAddress((void**)&yb,    g_yb);
    cudaGetSymbolAddress((void**)&yi,    g_yi);
    cudaGetSymbolAddress((void**)&h1,    g_h1);
    cudaGetSymbolAddress((void**)&h2,    g_h2);
    cudaGetSymbolAddress((void**)&tmp,   g_tmp);
    cudaGetSymbolAddress((void**)&g1,    g_g1);
    cudaGetSymbolAddress((void**)&dc,    g_dc);
    cudaGetSymbolAddress((void**)&ctx,   g_ctx);
    cudaGetSymbolAddress((void**)&ew,    g_ew);
    cudaGetSymbolAddress((void**)&val,   g_val);
    cudaGetSymbolAddress((void**)&dis,   g_dis);
    cudaGetSymbolAddress((void**)&diag,  g_diag);
    cudaGetSymbolAddress((void**)&deg,   g_deg);
    cudaGetSymbolAddress((void**)&rowcnt,g_rowcnt);
    cudaGetSymbolAddress((void**)&fill,  g_fill);
    cudaGetSymbolAddress((void**)&rowptr,g_rowptr);
    cudaGetSymbolAddress((void**)&colidx,g_colidx);

    // ---- 1. Build normalized Laplacian as CSR (once per launch) ----
    init_graph_kernel<<<NN / 256, 256>>>(deg, rowcnt, fill);
    edgew_kernel<<<EE / 256, 256>>>(edge_attr, ew_w1, ew_b1, ew_w2, ew_b2, ew);
    count_kernel<<<EE / 256, 256>>>(edge_idx, rowcnt, deg);
    disdiag_kernel<<<NN / 256, 256>>>(deg, dis, diag);
    scan_kernel<<<1, 256>>>(rowcnt, rowptr);
    scatter_kernel<<<EE / 256, 256>>>(edge_idx, ew, dis, rowptr, fill, colidx, val);

    // ---- 2. Constant context projection (absorbs td_b1) ----
    ctxproj_kernel<<<BB, HH>>>(context, td_w1, td_b1, ctx);

    // ---- 3. y0 = state ----
    copy_kernel<<<TOT / 4 / 256, 256>>>((float4*)ya, (const float4*)state);

    Wts w;
    w.td_w1 = td_w1; w.td_b2 = td_b2; w.ln1_g = ln1_g; w.ln1_b = ln1_b;
    w.td_w2 = td_w2; w.ln2_g = ln2_g; w.ln2_b = ln2_b;
    w.td_w3 = td_w3; w.td_b3 = td_b3;
    w.df_w1 = df_w1; w.df_b1 = df_b1; w.df_w2 = df_w2; w.df_b2 = df_b2;
    w.h1 = h1; w.h2 = h2; w.tmp = tmp; w.g1 = g1; w.dc = dc; w.ctx = ctx;
    w.rowptr = rowptr; w.colidx = colidx; w.val = val; w.diag = diag;

    // ---- 4. dopri5, 4 fixed steps, FSAL reuse ----
    const double dt = 0.25;
    const double A2[1] = {1.0 / 5};
    const double A3[2] = {3.0 / 40, 9.0 / 40};
    const double A4[3] = {44.0 / 45, -56.0 / 15, 32.0 / 9};
    const double A5[4] = {19372.0 / 6561, -25360.0 / 2187, 64448.0 / 6561, -212.0 / 729};
    const double A6[5] = {9017.0 / 3168, -355.0 / 33, 46732.0 / 5247, 49.0 / 176, -5103.0 / 18656};
    const double BW[6] = {35.0 / 384, 0.0, 500.0 / 1113, 125.0 / 192, -2187.0 / 6784, 11.0 / 84};
    const double* Arows[5] = {A2, A3, A4, A5, A6};

    float* kp[7];
    for (int i = 0; i < 7; i++) kp[i] = kbuf + (size_t)i * TOT;

    float* ycur = ya;
    float* yoth = yb;
    const int nAx = TOT / 4 / 256;

    for (int s = 0; s < 4; ++s) {
        if (s == 0) feval(ycur, kp[0], w);   // else FSAL: kp[0] = prev step's k7

        for (int i = 1; i <= 5; ++i) {
            const double* a = Arows[i - 1];
            const float4* ks[6] = {nullptr, nullptr, nullptr, nullptr, nullptr, nullptr};
            float cs[6] = {0, 0, 0, 0, 0, 0};
            for (int j = 0; j < i; j++) { ks[j] = (const float4*)kp[j]; cs[j] = (float)(dt * a[j]); }
            axpy_kernel<<<nAx, 256>>>((float4*)yi, (const float4*)ycur,
                                      ks[0], ks[1], ks[2], ks[3], ks[4], ks[5],
                                      cs[0], cs[1], cs[2], cs[3], cs[4], cs[5]);
            feval(yi, kp[i], w);
        }

        float* ynext = (s == 3) ? (float*)d_out : yoth;
        axpy_kernel<<<nAx, 256>>>((float4*)ynext, (const float4*)ycur,
                                  (const float4*)kp[0], nullptr,
                                  (const float4*)kp[2], (const float4*)kp[3],
                                  (const float4*)kp[4], (const float4*)kp[5],
                                  (float)(dt * BW[0]), 0.f,
                                  (float)(dt * BW[2]), (float)(dt * BW[3]),
                                  (float)(dt * BW[4]), (float)(dt * BW[5]));

        if (s < 3) {
            // FSAL: k7 = f(ynew) becomes next step's k1
            feval(ynext, kp[6], w);
            float* t = kp[0]; kp[0] = kp[6]; kp[6] = t;
            yoth = ycur;
            ycur = ynext;
        }
    }
}

// round 14
// speedup vs baseline: 1.1225x; 1.0560x over previous
#include <cuda_runtime.h>
#include <math.h>

// Fixed problem shapes
#define BB 4
#define NN 2048
#define FF 256
#define HH 512
#define EE 65536
#define ROWS (BB*NN)          // 8192
#define TOT  (ROWS*FF)        // 2097152

// ---------------- scratch (device globals; no cudaMalloc allowed) ----------
__device__ float g_kbuf[7 * TOT];
__device__ float g_ya[TOT];
__device__ float g_yb[TOT];
__device__ float g_yi[TOT];
__device__ float g_h1[ROWS * HH];
__device__ float g_h2[ROWS * HH];
__device__ float g_tmp[TOT];
__device__ float g_g1[TOT];
__device__ float g_dc[ROWS];
__device__ float g_ctx[BB * HH];
__device__ float g_ew[EE];
__device__ float g_val[EE];
__device__ float g_dis[NN];
__device__ float g_diag[NN];
__device__ int   g_deg[NN];
__device__ int   g_rowcnt[NN];
__device__ int   g_fill[NN];
__device__ int   g_rowptr[NN + 1];
__device__ int   g_colidx[EE];

// ---------------- graph / Laplacian build ----------------------------------

__global__ void init_graph_kernel(int* deg, int* rowcnt, int* fill) {
    int i = blockIdx.x * 256 + threadIdx.x;
    if (i < NN) { deg[i] = 1; rowcnt[i] = 0; fill[i] = 0; }  // deg=1: self loop
}

__global__ void edgew_kernel(const float* __restrict__ attr,
                             const float* __restrict__ w1, const float* __restrict__ b1,
                             const float* __restrict__ w2, const float* __restrict__ b2,
                             float* __restrict__ ew) {
    int e = blockIdx.x * 256 + threadIdx.x;
    if (e >= EE) return;
    float a = attr[e];
    float s = b2[0];
    #pragma unroll
    for (int j = 0; j < 32; j++) {
        float h = fmaxf(fmaf(a, w1[j], b1[j]), 0.f);
        s = fmaf(h, w2[j], s);
    }
    ew[e] = 1.f / (1.f + expf(-s));
}

__global__ void count_kernel(const int* __restrict__ ei, int* rowcnt, int* deg) {
    int e = blockIdx.x * 256 + threadIdx.x;
    if (e >= EE) return;
    atomicAdd(&rowcnt[ei[e]], 1);       // row
    atomicAdd(&deg[ei[EE + e]], 1);     // col (unweighted degree)
}

__global__ void disdiag_kernel(const int* __restrict__ deg, float* dis, float* diag) {
    int i = blockIdx.x * 256 + threadIdx.x;
    if (i >= NN) return;
    float d = rsqrtf((float)deg[i]);
    dis[i] = d;
    diag[i] = 1.f - d * d;   // L = I - adj; self-loop weight is dis[i]^2
}

// exclusive scan of 2048 counts -> rowptr (single block, 256 threads x 8)
__global__ void scan_kernel(const int* __restrict__ cnt, int* __restrict__ rowptr) {
    __shared__ int part[256];
    int t = threadIdx.x;
    int loc[8]; int s = 0;
    #pragma unroll
    for (int i = 0; i < 8; i++) { loc[i] = s; s += cnt[t * 8 + i]; }
    part[t] = s;
    __syncthreads();
    for (int off = 1; off < 256; off <<= 1) {
        int v = (t >= off) ? part[t - off] : 0;
        __syncthreads();
        part[t] += v;
        __syncthreads();
    }
    int base = t ? part[t - 1] : 0;
    #pragma unroll
    for (int i = 0; i < 8; i++) rowptr[t * 8 + i] = base + loc[i];
    if (t == 255) rowptr[NN] = part[255];
}

__global__ void scatter_kernel(const int* __restrict__ ei, const float* __restrict__ ew,
                               const float* __restrict__ dis, const int* __restrict__ rowptr,
                               int* fill, int* __restrict__ colidx, float* __restrict__ val) {
    int e = blockIdx.x * 256 + threadIdx.x;
    if (e >= EE) return;
    int r = ei[e], c = ei[EE + e];
    int pos = rowptr[r] + atomicAdd(&fill[r], 1);
    colidx[pos] = c;
    val[pos] = dis[r] * ew[e] * dis[c];
}

// ---------------- context projection (once per launch) ---------------------
__global__ void ctxproj_kernel(const float* __restrict__ context,
                               const float* __restrict__ w1, const float* __restrict__ b1,
                               float* __restrict__ out) {
    int b = blockIdx.x, n = threadIdx.x;  // 512 threads
    float s = b1[n];
    for (int k = 0; k < FF; k++)
        s = fmaf(context[b * FF + k], w1[(size_t)(FF + k) * HH + n], s);
    out[b * HH + n] = s;
}

// ---------------- SGEMM, packed fp32x2, K-paired accumulators ---------------
// C[M,N] = A[M,K] @ B[K,N] (+ biases, opt relu)
// BM=128, BN=64, BK=32 (16 k-pairs), 256 threads, 8 rows x 4 cols per thread.
// acc lanes: lo = even-k partial sum, hi = odd-k partial sum; summed at end.
// A tile: float2 As2[kp][row]  (row-contiguous; ra loads are warp-broadcast)
// B tile: float  Bsf[col][k], stride 34; thread cols at stride 16 ->
//         rb LDS.64 lane bank step = 2 -> conflict-free.
#define AS2_STRIDE 130   // float2 units per kp-row (128 + pad)
#define BSF_STRIDE 34    // floats per col (32 + pad)

__global__ __launch_bounds__(256, 2) void sgemm_kernel(
    const float* __restrict__ A, const float* __restrict__ B,
    float* __restrict__ C, int M, int N, int K, int ldb,
    const float* __restrict__ colBias,      // [N] or null
    const float* __restrict__ batchBias,    // [(row>>11)*N + col] or null
    int doRelu)
{
    __shared__ __align__(16) float2 As2[16 * AS2_STRIDE];
    __shared__ float Bsf[64 * BSF_STRIDE];
    int tid = threadIdx.x;
    int bn = blockIdx.x, bm = blockIdx.y;
    int tr = tid >> 4;            // 0..15 -> rows tr*8 .. tr*8+7
    int tc = tid & 15;            // cols tc + 16j, j = 0..3

    // A staging: 128 rows x 32 k, float4 per row chunk
    int aRow = tid >> 3;          // 0..31 (+32*it)
    int aCol4 = (tid & 7) << 2;   // k offset 0..28 step 4
    // B staging: 32 k x 64 cols
    int bRow = tid >> 4;          // 0..15 (+16*it)
    int bCol = (tid & 15) << 2;   // 0..60 step 4

    const float* Ab = A + (size_t)bm * 128 * K;
    const float* Bb = B + (size_t)bn * 64;

    unsigned long long acc[8][4];
    #pragma unroll
    for (int i = 0; i < 8; i++)
        #pragma unroll
        for (int j = 0; j < 4; j++) acc[i][j] = 0ull;

    const float2* Arp = As2 + tr * 8;
    const float*  Brp = Bsf + tc * BSF_STRIDE;

    for (int k0 = 0; k0 < K; k0 += 32) {
        // A -> smem: float4 of 4 consecutive k = 2 k-pairs
        #pragma unroll
        for (int it = 0; it < 4; ++it) {
            int r = aRow + 32 * it;
            float4 v = *(const float4*)(Ab + (size_t)r * K + k0 + aCol4);
            int kp = aCol4 >> 1;   // 2c
            As2[(kp    ) * AS2_STRIDE + r] = make_float2(v.x, v.y);
            As2[(kp + 1) * AS2_STRIDE + r] = make_float2(v.z, v.w);
        }
        // B -> smem: coalesced row load, scattered col-major store
        #pragma unroll
        for (int it = 0; it < 2; ++it) {
            int r = bRow + 16 * it;
            float4 v = *(const float4*)(Bb + (size_t)(k0 + r) * ldb + bCol);
            Bsf[(bCol + 0) * BSF_STRIDE + r] = v.x;
            Bsf[(bCol + 1) * BSF_STRIDE + r] = v.y;
            Bsf[(bCol + 2) * BSF_STRIDE + r] = v.z;
            Bsf[(bCol + 3) * BSF_STRIDE + r] = v.w;
        }
        __syncthreads();

        #pragma unroll
        for (int kp = 0; kp < 16; kp++) {
            unsigned long long ra[8], rb[4];
            #pragma unroll
            for (int q = 0; q < 4; q++) {
                ulonglong2 t = *(const ulonglong2*)(Arp + kp * AS2_STRIDE + 2 * q);
                ra[2 * q] = t.x; ra[2 * q + 1] = t.y;
            }
            #pragma unroll
            for (int j = 0; j < 4; j++)
                rb[j] = *(const unsigned long long*)(Brp + j * 16 * BSF_STRIDE + 2 * kp);
            #pragma unroll
            for (int i = 0; i < 8; i++)
                #pragma unroll
                for (int j = 0; j < 4; j++)
                    asm("fma.rn.f32x2 %0, %1, %2, %0;"
                        : "+l"(acc[i][j]) : "l"(ra[i]), "l"(rb[j]));
        }
        __syncthreads();
    }

    // epilogue: sum even/odd-k partials, add biases, store scalars
    #pragma unroll
    for (int i = 0; i < 8; i++) {
        int row = bm * 128 + tr * 8 + i;
        float* Cr = C + (size_t)row * N + bn * 64;
        const float* bbr = batchBias ? batchBias + (size_t)(row >> 11) * N + bn * 64 : nullptr;
        #pragma unroll
        for (int j = 0; j < 4; j++) {
            int col = tc + 16 * j;
            float2 p = *reinterpret_cast<float2*>(&acc[i][j]);
            float v = p.x + p.y;
            if (colBias) v += colBias[bn * 64 + col];
            if (bbr) v += bbr[col];
            if (doRelu) v = fmaxf(v, 0.f);
            Cr[col] = v;
        }
    }
}

// ---------------- LayerNorm(width=512) + ReLU, in-place, two-pass ----------
__global__ __launch_bounds__(256) void ln_relu_kernel(float* __restrict__ x,
                                                      const float* __restrict__ g,
                                                      const float* __restrict__ b) {
    int row = blockIdx.x;
    float* xr = x + (size_t)row * HH;
    int t = threadIdx.x;
    float2 v = ((float2*)xr)[t];
    __shared__ float ws[8];
    __shared__ float mu_s, inv_s;
    int lane = t & 31, w = t >> 5;

    float s = v.x + v.y;
    #pragma unroll
    for (int o = 16; o; o >>= 1) s += __shfl_xor_sync(0xffffffffu, s, o);
    if (!lane) ws[w] = s;
    __syncthreads();
    if (t == 0) {
        float tot = 0.f;
        #pragma unroll
        for (int i = 0; i < 8; i++) tot += ws[i];
        mu_s = tot * (1.f / HH);
    }
    __syncthreads();
    float mu = mu_s;
    float dx = v.x - mu, dy = v.y - mu;
    s = dx * dx + dy * dy;
    #pragma unroll
    for (int o = 16; o; o >>= 1) s += __shfl_xor_sync(0xffffffffu, s, o);
    if (!lane) ws[w] = s;
    __syncthreads();
    if (t == 0) {
        float tot = 0.f;
        #pragma unroll
        for (int i = 0; i < 8; i++) tot += ws[i];
        inv_s = rsqrtf(tot * (1.f / HH) + 1e-5f);
    }
    __syncthreads();
    float inv = inv_s;
    float2 gv = ((const float2*)g)[t];
    float2 bv = ((const float2*)b)[t];
    float2 o;
    o.x = fmaxf(fmaf(dx * inv, gv.x, bv.x), 0.f);
    o.y = fmaxf(fmaf(dy * inv, gv.y, bv.y), 0.f);
    ((float2*)xr)[t] = o;
}

// ---------------- dcoef: sigmoid(row-dot) ----------------------------------
__global__ __launch_bounds__(256) void dcoef_kernel(const float* __restrict__ g1,
                                                    const float* __restrict__ w2,
                                                    const float* __restrict__ b2,
                                                    float* __restrict__ dc) {
    int lane = threadIdx.x & 31, w = threadIdx.x >> 5;
    int row = blockIdx.x * 8 + w;
    const float* r = g1 + (size_t)row * FF;
    float s = 0.f;
    #pragma unroll
    for (int j = 0; j < FF / 32; j++)
        s = fmaf(r[lane + j * 32], w2[lane + j * 32], s);
    #pragma unroll
    for (int o = 16; o; o >>= 1) s += __shfl_xor_sync(0xffffffffu, s, o);
    if (!lane) dc[row] = 1.f / (1.f + expf(-(s + b2[0])));
}

// ---------------- fused SpMM diffusion + combine ----------------------------
__global__ __launch_bounds__(256) void spmm_kernel(
    const float* __restrict__ y, const float* __restrict__ temporal,
    const float* __restrict__ dc, const int* __restrict__ rowptr,
    const int* __restrict__ colidx, const float* __restrict__ val,
    const float* __restrict__ diag, float* __restrict__ kout)
{
    int i = blockIdx.x, b = blockIdx.y, f = threadIdx.x;
    const float* yb = y + (size_t)b * NN * FF;
    float acc = diag[i] * yb[(size_t)i * FF + f];
    int e1 = rowptr[i + 1];
    for (int e = rowptr[i]; e < e1; ++e)
        acc = fmaf(-val[e], yb[(size_t)colidx[e] * FF + f], acc);
    size_t o = ((size_t)b * NN + i) * FF + f;
    kout[o] = temporal[o] - dc[b * NN + i] * acc;
}

// ---------------- stage combine: out = y + sum c_j * k_j -------------------
__global__ __launch_bounds__(256) void axpy_kernel(
    float4* __restrict__ out, const float4* __restrict__ y,
    const float4* k0, const float4* k1, const float4* k2,
    const float4* k3, const float4* k4, const float4* k5,
    float c0, float c1, float c2, float c3, float c4, float c5)
{
    int i = blockIdx.x * 256 + threadIdx.x;  // grid = TOT/4/256
    float4 v = y[i];
#define ACCK(kk, cc) if (kk) { float4 a = kk[i]; \
    v.x = fmaf(cc, a.x, v.x); v.y = fmaf(cc, a.y, v.y); \
    v.z = fmaf(cc, a.z, v.z); v.w = fmaf(cc, a.w, v.w); }
    ACCK(k0, c0) ACCK(k1, c1) ACCK(k2, c2) ACCK(k3, c3) ACCK(k4, c4) ACCK(k5, c5)
#undef ACCK
    out[i] = v;
}

__global__ void copy_kernel(float4* __restrict__ dst, const float4* __restrict__ src) {
    int i = blockIdx.x * 256 + threadIdx.x;
    dst[i] = src[i];
}

// ---------------- host orchestration ----------------------------------------

struct Wts {
    const float *td_w1, *td_b2, *ln1_g, *ln1_b, *td_w2, *ln2_g, *ln2_b,
                *td_w3, *td_b3, *df_w1, *df_b1, *df_w2, *df_b2;
    float *h1, *h2, *tmp, *g1, *dc, *ctx;
    const int *rowptr, *colidx;
    const float *val, *diag;
};

static void feval(const float* y, float* kout, const Wts& w) {
    dim3 gBig(HH / 64, ROWS / 128);     // (8, 64)
    dim3 gSmall(FF / 64, ROWS / 128);   // (4, 64)
    sgemm_kernel<<<gBig, 256>>>(y, w.td_w1, w.h1, ROWS, HH, FF, HH, nullptr, w.ctx, 0);
    ln_relu_kernel<<<ROWS, 256>>>(w.h1, w.ln1_g, w.ln1_b);
    sgemm_kernel<<<gBig, 256>>>(w.h1, w.td_w2, w.h2, ROWS, HH, HH, HH, w.td_b2, nullptr, 0);
    ln_relu_kernel<<<ROWS, 256>>>(w.h2, w.ln2_g, w.ln2_b);
    sgemm_kernel<<<gSmall, 256>>>(w.h2, w.td_w3, w.tmp, ROWS, FF, HH, FF, w.td_b3, nullptr, 0);
    sgemm_kernel<<<gSmall, 256>>>(y, w.df_w1, w.g1, ROWS, FF, FF, FF, w.df_b1, nullptr, 1);
    dcoef_kernel<<<ROWS / 8, 256>>>(w.g1, w.df_w2, w.df_b2, w.dc);
    spmm_kernel<<<dim3(NN, BB), 256>>>(y, w.tmp, w.dc, w.rowptr, w.colidx, w.val, w.diag, kout);
}

extern "C" void kernel_launch(void* const* d_in, const int* in_sizes, int n_in,
                              void* d_out, int out_size)
{
    const float* state     = (const float*)d_in[0];
    const float* context   = (const float*)d_in[1];
    const float* edge_attr = (const float*)d_in[2];
    const int*   edge_idx  = (const int*)  d_in[3];
    const float* ew_w1 = (const float*)d_in[4];
    const float* ew_b1 = (const float*)d_in[5];
    const float* ew_w2 = (const float*)d_in[6];
    const float* ew_b2 = (const float*)d_in[7];
    const float* td_w1 = (const float*)d_in[8];
    const float* td_b1 = (const float*)d_in[9];
    const float* ln1_g = (const float*)d_in[10];
    const float* ln1_b = (const float*)d_in[11];
    const float* td_w2 = (const float*)d_in[12];
    const float* td_b2 = (const float*)d_in[13];
    const float* ln2_g = (const float*)d_in[14];
    const float* ln2_b = (const float*)d_in[15];
    const float* td_w3 = (const float*)d_in[16];
    const float* td_b3 = (const float*)d_in[17];
    const float* df_w1 = (const float*)d_in[18];
    const float* df_b1 = (const float*)d_in[19];
    const float* df_w2 = (const float*)d_in[20];
    const float* df_b2 = (const float*)d_in[21];

    float *kbuf, *ya, *yb, *yi, *h1, *h2, *tmp, *g1, *dc, *ctx;
    float *ew, *val, *dis, *diag;
    int *deg, *rowcnt, *fill, *rowptr, *colidx;
    cudaGetSymbolAddress((void**)&kbuf,  g_kbuf);
    cudaGetSymbolAddress((void**)&ya,    g_ya);
    cudaGetSymbolAddress((void**)&yb,    g_yb);
    cudaGetSymbolAddress((void**)&yi,    g_yi);
    cudaGetSymbolAddress((void**)&h1,    g_h1);
    cudaGetSymbolAddress((void**)&h2,    g_h2);
    cudaGetSymbolAddress((void**)&tmp,   g_tmp);
    cudaGetSymbolAddress((void**)&g1,    g_g1);
    cudaGetSymbolAddress((void**)&dc,    g_dc);
    cudaGetSymbolAddress((void**)&ctx,   g_ctx);
    cudaGetSymbolAddress((void**)&ew,    g_ew);
    cudaGetSymbolAddress((void**)&val,   g_val);
    cudaGetSymbolAddress((void**)&dis,   g_dis);
    cudaGetSymbolAddress((void**)&diag,  g_diag);
    cudaGetSymbolAddress((void**)&deg,   g_deg);
    cudaGetSymbolAddress((void**)&rowcnt,g_rowcnt);
    cudaGetSymbolAddress((void**)&fill,  g_fill);
    cudaGetSymbolAddress((void**)&rowptr,g_rowptr);
    cudaGetSymbolAddress((void**)&colidx,g_colidx);

    // ---- 1. Build normalized Laplacian as CSR (once per launch) ----
    init_graph_kernel<<<NN / 256, 256>>>(deg, rowcnt, fill);
    edgew_kernel<<<EE / 256, 256>>>(edge_attr, ew_w1, ew_b1, ew_w2, ew_b2, ew);
    count_kernel<<<EE / 256, 256>>>(edge_idx, rowcnt, deg);
    disdiag_kernel<<<NN / 256, 256>>>(deg, dis, diag);
    scan_kernel<<<1, 256>>>(rowcnt, rowptr);
    scatter_kernel<<<EE / 256, 256>>>(edge_idx, ew, dis, rowptr, fill, colidx, val);

    // ---- 2. Constant context projection (absorbs td_b1) ----
    ctxproj_kernel<<<BB, HH>>>(context, td_w1, td_b1, ctx);

    // ---- 3. y0 = state ----
    copy_kernel<<<TOT / 4 / 256, 256>>>((float4*)ya, (const float4*)state);

    Wts w;
    w.td_w1 = td_w1; w.td_b2 = td_b2; w.ln1_g = ln1_g; w.ln1_b = ln1_b;
    w.td_w2 = td_w2; w.ln2_g = ln2_g; w.ln2_b = ln2_b;
    w.td_w3 = td_w3; w.td_b3 = td_b3;
    w.df_w1 = df_w1; w.df_b1 = df_b1; w.df_w2 = df_w2; w.df_b2 = df_b2;
    w.h1 = h1; w.h2 = h2; w.tmp = tmp; w.g1 = g1; w.dc = dc; w.ctx = ctx;
    w.rowptr = rowptr; w.colidx = colidx; w.val = val; w.diag = diag;

    // ---- 4. dopri5, 4 fixed steps, FSAL reuse ----
    const double dt = 0.25;
    const double A2[1] = {1.0 / 5};
    const double A3[2] = {3.0 / 40, 9.0 / 40};
    const double A4[3] = {44.0 / 45, -56.0 / 15, 32.0 / 9};
    const double A5[4] = {19372.0 / 6561, -25360.0 / 2187, 64448.0 / 6561, -212.0 / 729};
    const double A6[5] = {9017.0 / 3168, -355.0 / 33, 46732.0 / 5247, 49.0 / 176, -5103.0 / 18656};
    const double BW[6] = {35.0 / 384, 0.0, 500.0 / 1113, 125.0 / 192, -2187.0 / 6784, 11.0 / 84};
    const double* Arows[5] = {A2, A3, A4, A5, A6};

    float* kp[7];
    for (int i = 0; i < 7; i++) kp[i] = kbuf + (size_t)i * TOT;

    float* ycur = ya;
    float* yoth = yb;
    const int nAx = TOT / 4 / 256;

    for (int s = 0; s < 4; ++s) {
        if (s == 0) feval(ycur, kp[0], w);   // else FSAL: kp[0] = prev step's k7

        for (int i = 1; i <= 5; ++i) {
            const double* a = Arows[i - 1];
            const float4* ks[6] = {nullptr, nullptr, nullptr, nullptr, nullptr, nullptr};
            float cs[6] = {0, 0, 0, 0, 0, 0};
            for (int j = 0; j < i; j++) { ks[j] = (const float4*)kp[j]; cs[j] = (float)(dt * a[j]); }
            axpy_kernel<<<nAx, 256>>>((float4*)yi, (const float4*)ycur,
                                      ks[0], ks[1], ks[2], ks[3], ks[4], ks[5],
                                      cs[0], cs[1], cs[2], cs[3], cs[4], cs[5]);
            feval(yi, kp[i], w);
        }

        float* ynext = (s == 3) ? (float*)d_out : yoth;
        axpy_kernel<<<nAx, 256>>>((float4*)ynext, (const float4*)ycur,
                                  (const float4*)kp[0], nullptr,
                                  (const float4*)kp[2], (const float4*)kp[3],
                                  (const float4*)kp[4], (const float4*)kp[5],
                                  (float)(dt * BW[0]), 0.f,
                                  (float)(dt * BW[2]), (float)(dt * BW[3]),
                                  (float)(dt * BW[4]), (float)(dt * BW[5]));

        if (s < 3) {
            // FSAL: k7 = f(ynew) becomes next step's k1
            feval(ynext, kp[6], w);
            float* t = kp[0]; kp[0] = kp[6]; kp[6] = t;
            yoth = ycur;
            ycur = ynext;
        }
    }
}

// round 16
// speedup vs baseline: 2.0984x; 1.8694x over previous
#include <cuda_runtime.h>
#include <cuda_bf16.h>
#include <math.h>
#include <stdint.h>

// Fixed problem shapes
#define BB 4
#define NN 2048
#define FF 256
#define HH 512
#define EE 65536
#define ROWS (BB*NN)          // 8192
#define TOT  (ROWS*FF)        // 2097152

// ---------------- scratch (device globals; no cudaMalloc allowed) ----------
__device__ float g_kbuf[7 * TOT];
__device__ float g_ya[TOT];
__device__ float g_yb[TOT];
__device__ float g_yi[TOT];
__device__ float g_h1[ROWS * HH];
__device__ float g_h2[ROWS * HH];
__device__ float g_tmp[TOT];
__device__ float g_g1[TOT];
__device__ float g_dc[ROWS];
__device__ float g_ctx[BB * HH];
__device__ float g_ew[EE];
__device__ float g_val[EE];
__device__ float g_dis[NN];
__device__ float g_diag[NN];
__device__ int   g_deg[NN];
__device__ int   g_rowcnt[NN];
__device__ int   g_fill[NN];
__device__ int   g_rowptr[NN + 1];
__device__ int   g_colidx[EE];
// split-bf16 transposed weights: Wt[n][k]
__device__ __nv_bfloat16 g_w1t_h[HH * FF], g_w1t_l[HH * FF];   // [512][256]
__device__ __nv_bfloat16 g_w2t_h[HH * HH], g_w2t_l[HH * HH];   // [512][512]
__device__ __nv_bfloat16 g_w3t_h[FF * HH], g_w3t_l[FF * HH];   // [256][512]
__device__ __nv_bfloat16 g_dft_h[FF * FF], g_dft_l[FF * FF];   // [256][256]

// ---------------- mma helpers (sm_80+ baseline PTX, no arch-specific ops) ---
__device__ __forceinline__ uint32_t smem_to_u32(const void* p) {
    uint32_t a;
    asm("{ .reg .u64 t; cvta.to.shared.u64 t, %1; cvt.u32.u64 %0, t; }"
        : "=r"(a) : "l"(p));
    return a;
}
__device__ __forceinline__ void ldmx4(uint32_t* r, uint32_t addr) {
    asm volatile("ldmatrix.sync.aligned.m8n8.x4.shared.b16 {%0,%1,%2,%3}, [%4];"
        : "=r"(r[0]), "=r"(r[1]), "=r"(r[2]), "=r"(r[3]) : "r"(addr));
}
__device__ __forceinline__ void mma16816(float* d, const uint32_t* a,
                                         uint32_t b0, uint32_t b1) {
    asm volatile("mma.sync.aligned.m16n8k16.row.col.f32.bf16.bf16.f32 "
        "{%0,%1,%2,%3}, {%4,%5,%6,%7}, {%8,%9}, {%0,%1,%2,%3};"
        : "+f"(d[0]), "+f"(d[1]), "+f"(d[2]), "+f"(d[3])
        : "r"(a[0]), "r"(a[1]), "r"(a[2]), "r"(a[3]), "r"(b0), "r"(b1));
}

// ---------------- HMMA GEMM: C[M,Nout] = A[M,K] @ Wt^T ----------------------
// Wt split bf16 [Nout][K] (K-major = mma .col B operand layout).
// Block tile 128x128, BK=32; 8 warps, warp tile 32x64.
// D += Ahi*Bhi + Ahi*Blo + Alo*Bhi (fp32 accum).
#define LDP 40   // bf16 stride per row: 80 B -> ldmatrix conflict-free

__global__ __launch_bounds__(256, 2) void mma_gemm(
    const float* __restrict__ A, const __nv_bfloat16* __restrict__ Bhi,
    const __nv_bfloat16* __restrict__ Blo, float* __restrict__ C,
    int K, int Nout, const float* __restrict__ colBias,
    const float* __restrict__ batchBias, int doRelu)
{
    __shared__ __nv_bfloat16 Ah[128 * LDP], Al[128 * LDP];
    __shared__ __nv_bfloat16 Bh[128 * LDP], Bl[128 * LDP];
    int tid = threadIdx.x, lane = tid & 31, wid = tid >> 5;
    int wm = wid & 3, wn = wid >> 2;       // warp row base 32*wm, col base 64*wn
    int bn = blockIdx.x, bm = blockIdx.y;

    float acc[2][8][4];
    #pragma unroll
    for (int i = 0; i < 2; i++)
        #pragma unroll
        for (int j = 0; j < 8; j++)
            #pragma unroll
            for (int q = 0; q < 4; q++) acc[i][j][q] = 0.f;

    uint32_t ahb = smem_to_u32(Ah), alb = smem_to_u32(Al);
    uint32_t bhb = smem_to_u32(Bh), blb = smem_to_u32(Bl);

    for (int k0 = 0; k0 < K; k0 += 32) {
        // ---- stage A: fp32 -> split bf16 hi/lo ----
        #pragma unroll
        for (int it = 0; it < 2; ++it) {
            int g = it * 256 + tid;            // 512 granules of 8 floats
            int row = g >> 2, k8 = (g & 3) << 3;
            const float* src = A + (size_t)(bm * 128 + row) * K + k0 + k8;
            float4 v0 = *(const float4*)src;
            float4 v1 = *(const float4*)(src + 4);
            float vv[8] = {v0.x, v0.y, v0.z, v0.w, v1.x, v1.y, v1.z, v1.w};
            union { __nv_bfloat162 b2[4]; uint4 u; } H, L;
            #pragma unroll
            for (int j = 0; j < 4; ++j) {
                float a0 = vv[2 * j], a1 = vv[2 * j + 1];
                __nv_bfloat16 h0 = __float2bfloat16_rn(a0);
                __nv_bfloat16 h1 = __float2bfloat16_rn(a1);
                H.b2[j].x = h0; H.b2[j].y = h1;
                L.b2[j].x = __float2bfloat16_rn(a0 - __bfloat162float(h0));
                L.b2[j].y = __float2bfloat16_rn(a1 - __bfloat162float(h1));
            }
            *(uint4*)&Ah[row * LDP + k8] = H.u;
            *(uint4*)&Al[row * LDP + k8] = L.u;
        }
        // ---- stage B: straight copies (already split bf16, K-major) ----
        #pragma unroll
        for (int it = 0; it < 2; ++it) {
            int g = it * 256 + tid;
            int n = g >> 2, k8 = (g & 3) << 3;
            size_t go = (size_t)(bn * 128 + n) * K + k0 + k8;
            *(uint4*)&Bh[n * LDP + k8] = *(const uint4*)(Bhi + go);
            *(uint4*)&Bl[n * LDP + k8] = *(const uint4*)(Blo + go);
        }
        __syncthreads();

        #pragma unroll
        for (int ks = 0; ks < 2; ++ks) {
            uint32_t ah[2][4], al[2][4];
            #pragma unroll
            for (int mt = 0; mt < 2; ++mt) {
                uint32_t off = (uint32_t)(((wm * 32 + mt * 16 + (lane & 15)) * LDP
                                           + ks * 16 + (lane >> 4) * 8) * 2);
                ldmx4(ah[mt], ahb + off);
                ldmx4(al[mt], alb + off);
            }
            #pragma unroll
            for (int ph = 0; ph < 2; ++ph) {
                uint32_t bh[2][4], bl[2][4];
                #pragma unroll
                for (int pp = 0; pp < 2; ++pp) {
                    int p = ph * 2 + pp;
                    uint32_t off = (uint32_t)(((wn * 64 + p * 16 + (lane & 7)
                                                + ((lane >> 4) << 3)) * LDP
                                               + ks * 16 + ((lane >> 3) & 1) * 8) * 2);
                    ldmx4(bh[pp], bhb + off);
                    ldmx4(bl[pp], blb + off);
                }
                #pragma unroll
                for (int mt = 0; mt < 2; ++mt)
                    #pragma unroll
                    for (int pp = 0; pp < 2; ++pp) {
                        int nt = (ph * 2 + pp) * 2;
                        mma16816(acc[mt][nt],     ah[mt], bh[pp][0], bh[pp][1]);
                        mma16816(acc[mt][nt],     ah[mt], bl[pp][0], bl[pp][1]);
                        mma16816(acc[mt][nt],     al[mt], bh[pp][0], bh[pp][1]);
                        mma16816(acc[mt][nt + 1], ah[mt], bh[pp][2], bh[pp][3]);
                        mma16816(acc[mt][nt + 1], ah[mt], bl[pp][2], bl[pp][3]);
                        mma16816(acc[mt][nt + 1], al[mt], bh[pp][2], bh[pp][3]);
                    }
            }
        }
        __syncthreads();
    }

    // ---- epilogue ----
    #pragma unroll
    for (int mt = 0; mt < 2; ++mt) {
        #pragma unroll
        for (int half = 0; half < 2; ++half) {
            int row = bm * 128 + wm * 32 + mt * 16 + half * 8 + (lane >> 2);
            float* Cr = C + (size_t)row * Nout;
            const float* bbr = batchBias
                ? batchBias + (size_t)(row >> 11) * Nout : nullptr;
            #pragma unroll
            for (int nt = 0; nt < 8; ++nt) {
                int col = bn * 128 + wn * 64 + nt * 8 + 2 * (lane & 3);
                float x = acc[mt][nt][half * 2 + 0];
                float y = acc[mt][nt][half * 2 + 1];
                if (colBias) {
                    float2 cb = *(const float2*)(colBias + col);
                    x += cb.x; y += cb.y;
                }
                if (bbr) {
                    float2 bb = *(const float2*)(bbr + col);
                    x += bb.x; y += bb.y;
                }
                if (doRelu) { x = fmaxf(x, 0.f); y = fmaxf(y, 0.f); }
                *(float2*)(Cr + col) = make_float2(x, y);
            }
        }
    }
}

// ---------------- weight transpose + bf16 split (once per launch) -----------
__global__ void wsplit_kernel(const float* __restrict__ W, int K, int N,
                              __nv_bfloat16* __restrict__ hi,
                              __nv_bfloat16* __restrict__ lo) {
    int idx = blockIdx.x * 256 + threadIdx.x;   // = n*K + k
    if (idx >= N * K) return;
    int n = idx / K, k = idx - n * K;
    float v = W[(size_t)k * N + n];
    __nv_bfloat16 h = __float2bfloat16_rn(v);
    hi[idx] = h;
    lo[idx] = __float2bfloat16_rn(v - __bfloat162float(h));
}

// ---------------- graph / Laplacian build ----------------------------------

__global__ void init_graph_kernel(int* deg, int* rowcnt, int* fill) {
    int i = blockIdx.x * 256 + threadIdx.x;
    if (i < NN) { deg[i] = 1; rowcnt[i] = 0; fill[i] = 0; }
}

__global__ void edgew_kernel(const float* __restrict__ attr,
                             const float* __restrict__ w1, const float* __restrict__ b1,
                             const float* __restrict__ w2, const float* __restrict__ b2,
                             float* __restrict__ ew) {
    int e = blockIdx.x * 256 + threadIdx.x;
    if (e >= EE) return;
    float a = attr[e];
    float s = b2[0];
    #pragma unroll
    for (int j = 0; j < 32; j++) {
        float h = fmaxf(fmaf(a, w1[j], b1[j]), 0.f);
        s = fmaf(h, w2[j], s);
    }
    ew[e] = 1.f / (1.f + expf(-s));
}

__global__ void count_kernel(const int* __restrict__ ei, int* rowcnt, int* deg) {
    int e = blockIdx.x * 256 + threadIdx.x;
    if (e >= EE) return;
    atomicAdd(&rowcnt[ei[e]], 1);
    atomicAdd(&deg[ei[EE + e]], 1);
}

__global__ void disdiag_kernel(const int* __restrict__ deg, float* dis, float* diag) {
    int i = blockIdx.x * 256 + threadIdx.x;
    if (i >= NN) return;
    float d = rsqrtf((float)deg[i]);
    dis[i] = d;
    diag[i] = 1.f - d * d;
}

__global__ void scan_kernel(const int* __restrict__ cnt, int* __restrict__ rowptr) {
    __shared__ int part[256];
    int t = threadIdx.x;
    int loc[8]; int s = 0;
    #pragma unroll
    for (int i = 0; i < 8; i++) { loc[i] = s; s += cnt[t * 8 + i]; }
    part[t] = s;
    __syncthreads();
    for (int off = 1; off < 256; off <<= 1) {
        int v = (t >= off) ? part[t - off] : 0;
        __syncthreads();
        part[t] += v;
        __syncthreads();
    }
    int base = t ? part[t - 1] : 0;
    #pragma unroll
    for (int i = 0; i < 8; i++) rowptr[t * 8 + i] = base + loc[i];
    if (t == 255) rowptr[NN] = part[255];
}

__global__ void scatter_kernel(const int* __restrict__ ei, const float* __restrict__ ew,
                               const float* __restrict__ dis, const int* __restrict__ rowptr,
                               int* fill, int* __restrict__ colidx, float* __restrict__ val) {
    int e = blockIdx.x * 256 + threadIdx.x;
    if (e >= EE) return;
    int r = ei[e], c = ei[EE + e];
    int pos = rowptr[r] + atomicAdd(&fill[r], 1);
    colidx[pos] = c;
    val[pos] = dis[r] * ew[e] * dis[c];
}

// ---------------- context projection ----------------------------------------
__global__ void ctxproj_kernel(const float* __restrict__ context,
                               const float* __restrict__ w1, const float* __restrict__ b1,
                               float* __restrict__ out) {
    int b = blockIdx.x, n = threadIdx.x;
    float s = b1[n];
    for (int k = 0; k < FF; k++)
        s = fmaf(context[b * FF + k], w1[(size_t)(FF + k) * HH + n], s);
    out[b * HH + n] = s;
}

// ---------------- LayerNorm(width=512) + ReLU, in-place --------------------
__global__ __launch_bounds__(256) void ln_relu_kernel(float* __restrict__ x,
                                                      const float* __restrict__ g,
                                                      const float* __restrict__ b) {
    int row = blockIdx.x;
    float* xr = x + (size_t)row * HH;
    int t = threadIdx.x;
    float2 v = ((float2*)xr)[t];
    __shared__ float ws[8];
    __shared__ float mu_s, inv_s;
    int lane = t & 31, w = t >> 5;

    float s = v.x + v.y;
    #pragma unroll
    for (int o = 16; o; o >>= 1) s += __shfl_xor_sync(0xffffffffu, s, o);
    if (!lane) ws[w] = s;
    __syncthreads();
    if (t == 0) {
        float tot = 0.f;
        #pragma unroll
        for (int i = 0; i < 8; i++) tot += ws[i];
        mu_s = tot * (1.f / HH);
    }
    __syncthreads();
    float mu = mu_s;
    float dx = v.x - mu, dy = v.y - mu;
    s = dx * dx + dy * dy;
    #pragma unroll
    for (int o = 16; o; o >>= 1) s += __shfl_xor_sync(0xffffffffu, s, o);
    if (!lane) ws[w] = s;
    __syncthreads();
    if (t == 0) {
        float tot = 0.f;
        #pragma unroll
        for (int i = 0; i < 8; i++) tot += ws[i];
        inv_s = rsqrtf(tot * (1.f / HH) + 1e-5f);
    }
    __syncthreads();
    float inv = inv_s;
    float2 gv = ((const float2*)g)[t];
    float2 bv = ((const float2*)b)[t];
    float2 o;
    o.x = fmaxf(fmaf(dx * inv, gv.x, bv.x), 0.f);
    o.y = fmaxf(fmaf(dy * inv, gv.y, bv.y), 0.f);
    ((float2*)xr)[t] = o;
}

// ---------------- dcoef: sigmoid(row-dot) ----------------------------------
__global__ __launch_bounds__(256) void dcoef_kernel(const float* __restrict__ g1,
                                                    const float* __restrict__ w2,
                                                    const float* __restrict__ b2,
                                                    float* __restrict__ dc) {
    int lane = threadIdx.x & 31, w = threadIdx.x >> 5;
    int row = blockIdx.x * 8 + w;
    const float* r = g1 + (size_t)row * FF;
    float s = 0.f;
    #pragma unroll
    for (int j = 0; j < FF / 32; j++)
        s = fmaf(r[lane + j * 32], w2[lane + j * 32], s);
    #pragma unroll
    for (int o = 16; o; o >>= 1) s += __shfl_xor_sync(0xffffffffu, s, o);
    if (!lane) dc[row] = 1.f / (1.f + expf(-(s + b2[0])));
}

// ---------------- fused SpMM diffusion + combine ----------------------------
__global__ __launch_bounds__(256) void spmm_kernel(
    const float* __restrict__ y, const float* __restrict__ temporal,
    const float* __restrict__ dc, const int* __restrict__ rowptr,
    const int* __restrict__ colidx, const float* __restrict__ val,
    const float* __restrict__ diag, float* __restrict__ kout)
{
    int i = blockIdx.x, b = blockIdx.y, f = threadIdx.x;
    const float* yb = y + (size_t)b * NN * FF;
    float acc = diag[i] * yb[(size_t)i * FF + f];
    int e1 = rowptr[i + 1];
    for (int e = rowptr[i]; e < e1; ++e)
        acc = fmaf(-val[e], yb[(size_t)colidx[e] * FF + f], acc);
    size_t o = ((size_t)b * NN + i) * FF + f;
    kout[o] = temporal[o] - dc[b * NN + i] * acc;
}

// ---------------- stage combine: out = y + sum c_j * k_j -------------------
__global__ __launch_bounds__(256) void axpy_kernel(
    float4* __restrict__ out, const float4* __restrict__ y,
    const float4* k0, const float4* k1, const float4* k2,
    const float4* k3, const float4* k4, const float4* k5,
    float c0, float c1, float c2, float c3, float c4, float c5)
{
    int i = blockIdx.x * 256 + threadIdx.x;
    float4 v = y[i];
#define ACCK(kk, cc) if (kk) { float4 a = kk[i]; \
    v.x = fmaf(cc, a.x, v.x); v.y = fmaf(cc, a.y, v.y); \
    v.z = fmaf(cc, a.z, v.z); v.w = fmaf(cc, a.w, v.w); }
    ACCK(k0, c0) ACCK(k1, c1) ACCK(k2, c2) ACCK(k3, c3) ACCK(k4, c4) ACCK(k5, c5)
#undef ACCK
    out[i] = v;
}

__global__ void copy_kernel(float4* __restrict__ dst, const float4* __restrict__ src) {
    int i = blockIdx.x * 256 + threadIdx.x;
    dst[i] = src[i];
}

// ---------------- host orchestration ----------------------------------------

struct Wts {
    const float *td_b2, *ln1_g, *ln1_b, *ln2_g, *ln2_b, *td_b3,
                *df_b1, *df_w2, *df_b2;
    float *h1, *h2, *tmp, *g1, *dc, *ctx;
    const int *rowptr, *colidx;
    const float *val, *diag;
    const __nv_bfloat16 *w1h, *w1l, *w2h, *w2l, *w3h, *w3l, *dfh, *dfl;
};

static void feval(const float* y, float* kout, const Wts& w) {
    mma_gemm<<<dim3(4, 64), 256>>>(y, w.w1h, w.w1l, w.h1, FF, HH, nullptr, w.ctx, 0);
    ln_relu_kernel<<<ROWS, 256>>>(w.h1, w.ln1_g, w.ln1_b);
    mma_gemm<<<dim3(4, 64), 256>>>(w.h1, w.w2h, w.w2l, w.h2, HH, HH, w.td_b2, nullptr, 0);
    ln_relu_kernel<<<ROWS, 256>>>(w.h2, w.ln2_g, w.ln2_b);
    mma_gemm<<<dim3(2, 64), 256>>>(w.h2, w.w3h, w.w3l, w.tmp, HH, FF, w.td_b3, nullptr, 0);
    mma_gemm<<<dim3(2, 64), 256>>>(y, w.dfh, w.dfl, w.g1, FF, FF, w.df_b1, nullptr, 1);
    dcoef_kernel<<<ROWS / 8, 256>>>(w.g1, w.df_w2, w.df_b2, w.dc);
    spmm_kernel<<<dim3(NN, BB), 256>>>(y, w.tmp, w.dc, w.rowptr, w.colidx, w.val, w.diag, kout);
}

extern "C" void kernel_launch(void* const* d_in, const int* in_sizes, int n_in,
                              void* d_out, int out_size)
{
    const float* state     = (const float*)d_in[0];
    const float* context   = (const float*)d_in[1];
    const float* edge_attr = (const float*)d_in[2];
    const int*   edge_idx  = (const int*)  d_in[3];
    const float* ew_w1 = (const float*)d_in[4];
    const float* ew_b1 = (const float*)d_in[5];
    const float* ew_w2 = (const float*)d_in[6];
    const float* ew_b2 = (const float*)d_in[7];
    const float* td_w1 = (const float*)d_in[8];
    const float* td_b1 = (const float*)d_in[9];
    const float* ln1_g = (const float*)d_in[10];
    const float* ln1_b = (const float*)d_in[11];
    const float* td_w2 = (const float*)d_in[12];
    const float* td_b2 = (const float*)d_in[13];
    const float* ln2_g = (const float*)d_in[14];
    const float* ln2_b = (const float*)d_in[15];
    const float* td_w3 = (const float*)d_in[16];
    const float* td_b3 = (const float*)d_in[17];
    const float* df_w1 = (const float*)d_in[18];
    const float* df_b1 = (const float*)d_in[19];
    const float* df_w2 = (const float*)d_in[20];
    const float* df_b2 = (const float*)d_in[21];

    float *kbuf, *ya, *yb, *yi, *h1, *h2, *tmp, *g1, *dc, *ctx;
    float *ew, *val, *dis, *diag;
    int *deg, *rowcnt, *fill, *rowptr, *colidx;
    __nv_bfloat16 *w1h, *w1l, *w2h, *w2l, *w3h, *w3l, *dfh, *dfl;
    cudaGetSymbolAddress((void**)&kbuf,  g_kbuf);
    cudaGetSymbolAddress((void**)&ya,    g_ya);
    cudaGetSymbolAddress((void**)&yb,    g_yb);
    cudaGetSymbolAddress((void**)&yi,    g_yi);
    cudaGetSymbolAddress((void**)&h1,    g_h1);
    cudaGetSymbolAddress((void**)&h2,    g_h2);
    cudaGetSymbolAddress((void**)&tmp,   g_tmp);
    cudaGetSymbolAddress((void**)&g1,    g_g1);
    cudaGetSymbolAddress((void**)&dc,    g_dc);
    cudaGetSymbolAddress((void**)&ctx,   g_ctx);
    cudaGetSymbolAddress((void**)&ew,    g_ew);
    cudaGetSymbolAddress((void**)&val,   g_val);
    cudaGetSymbolAddress((void**)&dis,   g_dis);
    cudaGetSymbolAddress((void**)&diag,  g_diag);
    cudaGetSymbolAddress((void**)&deg,   g_deg);
    cudaGetSymbolAddress((void**)&rowcnt,g_rowcnt);
    cudaGetSymbolAddress((void**)&fill,  g_fill);
    cudaGetSymbolAddress((void**)&rowptr,g_rowptr);
    cudaGetSymbolAddress((void**)&colidx,g_colidx);
    cudaGetSymbolAddress((void**)&w1h, g_w1t_h);
    cudaGetSymbolAddress((void**)&w1l, g_w1t_l);
    cudaGetSymbolAddress((void**)&w2h, g_w2t_h);
    cudaGetSymbolAddress((void**)&w2l, g_w2t_l);
    cudaGetSymbolAddress((void**)&w3h, g_w3t_h);
    cudaGetSymbolAddress((void**)&w3l, g_w3t_l);
    cudaGetSymbolAddress((void**)&dfh, g_dft_h);
    cudaGetSymbolAddress((void**)&dfl, g_dft_l);

    // ---- 1. Build normalized Laplacian as CSR ----
    init_graph_kernel<<<NN / 256, 256>>>(deg, rowcnt, fill);
    edgew_kernel<<<EE / 256, 256>>>(edge_attr, ew_w1, ew_b1, ew_w2, ew_b2, ew);
    count_kernel<<<EE / 256, 256>>>(edge_idx, rowcnt, deg);
    disdiag_kernel<<<NN / 256, 256>>>(deg, dis, diag);
    scan_kernel<<<1, 256>>>(rowcnt, rowptr);
    scatter_kernel<<<EE / 256, 256>>>(edge_idx, ew, dis, rowptr, fill, colidx, val);

    // ---- 2. Constant context projection + weight transpose/split ----
    ctxproj_kernel<<<BB, HH>>>(context, td_w1, td_b1, ctx);
    wsplit_kernel<<<(HH * FF + 255) / 256, 256>>>(td_w1, FF, HH, w1h, w1l);  // rows 0..255
    wsplit_kernel<<<(HH * HH + 255) / 256, 256>>>(td_w2, HH, HH, w2h, w2l);
    wsplit_kernel<<<(FF * HH + 255) / 256, 256>>>(td_w3, HH, FF, w3h, w3l);
    wsplit_kernel<<<(FF * FF + 255) / 256, 256>>>(df_w1, FF, FF, dfh, dfl);

    // ---- 3. y0 = state ----
    copy_kernel<<<TOT / 4 / 256, 256>>>((float4*)ya, (const float4*)state);

    Wts w;
    w.td_b2 = td_b2; w.ln1_g = ln1_g; w.ln1_b = ln1_b;
    w.ln2_g = ln2_g; w.ln2_b = ln2_b; w.td_b3 = td_b3;
    w.df_b1 = df_b1; w.df_w2 = df_w2; w.df_b2 = df_b2;
    w.h1 = h1; w.h2 = h2; w.tmp = tmp; w.g1 = g1; w.dc = dc; w.ctx = ctx;
    w.rowptr = rowptr; w.colidx = colidx; w.val = val; w.diag = diag;
    w.w1h = w1h; w.w1l = w1l; w.w2h = w2h; w.w2l = w2l;
    w.w3h = w3h; w.w3l = w3l; w.dfh = dfh; w.dfl = dfl;

    // ---- 4. dopri5, 4 fixed steps, FSAL reuse ----
    const double dt = 0.25;
    const double A2[1] = {1.0 / 5};
    const double A3[2] = {3.0 / 40, 9.0 / 40};
    const double A4[3] = {44.0 / 45, -56.0 / 15, 32.0 / 9};
    const double A5[4] = {19372.0 / 6561, -25360.0 / 2187, 64448.0 / 6561, -212.0 / 729};
    const double A6[5] = {9017.0 / 3168, -355.0 / 33, 46732.0 / 5247, 49.0 / 176, -5103.0 / 18656};
    const double BW[6] = {35.0 / 384, 0.0, 500.0 / 1113, 125.0 / 192, -2187.0 / 6784, 11.0 / 84};
    const double* Arows[5] = {A2, A3, A4, A5, A6};

    float* kp[7];
    for (int i = 0; i < 7; i++) kp[i] = kbuf + (size_t)i * TOT;

    float* ycur = ya;
    float* yoth = yb;
    const int nAx = TOT / 4 / 256;

    for (int s = 0; s < 4; ++s) {
        if (s == 0) feval(ycur, kp[0], w);   // else FSAL: kp[0] = prev step's k7

        for (int i = 1; i <= 5; ++i) {
            const double* a = Arows[i - 1];
            const float4* ks[6] = {nullptr, nullptr, nullptr, nullptr, nullptr, nullptr};
            float cs[6] = {0, 0, 0, 0, 0, 0};
            for (int j = 0; j < i; j++) { ks[j] = (const float4*)kp[j]; cs[j] = (float)(dt * a[j]); }
            axpy_kernel<<<nAx, 256>>>((float4*)yi, (const float4*)ycur,
                                      ks[0], ks[1], ks[2], ks[3], ks[4], ks[5],
                                      cs[0], cs[1], cs[2], cs[3], cs[4], cs[5]);
            feval(yi, kp[i], w);
        }

        float* ynext = (s == 3) ? (float*)d_out : yoth;
        axpy_kernel<<<nAx, 256>>>((float4*)ynext, (const float4*)ycur,
                                  (const float4*)kp[0], nullptr,
                                  (const float4*)kp[2], (const float4*)kp[3],
                                  (const float4*)kp[4], (const float4*)kp[5],
                                  (float)(dt * BW[0]), 0.f,
                                  (float)(dt * BW[2]), (float)(dt * BW[3]),
                                  (float)(dt * BW[4]), (float)(dt * BW[5]));

        if (s < 3) {
            feval(ynext, kp[6], w);
            float* t = kp[0]; kp[0] = kp[6]; kp[6] = t;
            yoth = ycur;
            ycur = ynext;
        }
    }
}

// round 17
// speedup vs baseline: 2.2560x; 1.0751x over previous
#include <cuda_runtime.h>
#include <cuda_bf16.h>
#include <math.h>
#include <stdint.h>

// Fixed problem shapes
#define BB 4
#define NN 2048
#define FF 256
#define HH 512
#define EE 65536
#define ROWS (BB*NN)          // 8192
#define TOT  (ROWS*FF)        // 2097152

// ---------------- scratch (device globals; no cudaMalloc allowed) ----------
__device__ float g_kbuf[7 * TOT];
__device__ float g_ya[TOT];
__device__ float g_yb[TOT];
__device__ float g_yi[TOT];
__device__ float g_h1[ROWS * HH];
__device__ float g_h2[ROWS * HH];
__device__ float g_tmp[TOT];
__device__ float g_g1[TOT];
__device__ float g_dc[ROWS];
__device__ float g_ctx[BB * HH];
__device__ float g_ew[EE];
__device__ float g_val[EE];
__device__ float g_dis[NN];
__device__ float g_diag[NN];
__device__ int   g_deg[NN];
__device__ int   g_rowcnt[NN];
__device__ int   g_fill[NN];
__device__ int   g_rowptr[NN + 1];
__device__ int   g_colidx[EE];
// split-bf16 transposed weights: Wt[n][k]
__device__ __nv_bfloat16 g_w1t_h[HH * FF], g_w1t_l[HH * FF];
__device__ __nv_bfloat16 g_w2t_h[HH * HH], g_w2t_l[HH * HH];
__device__ __nv_bfloat16 g_w3t_h[FF * HH], g_w3t_l[FF * HH];
__device__ __nv_bfloat16 g_dft_h[FF * FF], g_dft_l[FF * FF];
// split-bf16 activations (producers fuse the split)
__device__ __nv_bfloat16 g_ysh[TOT],       g_ysl[TOT];        // current y
__device__ __nv_bfloat16 g_h1h[ROWS * HH], g_h1l[ROWS * HH];  // ln1 out
__device__ __nv_bfloat16 g_h2h[ROWS * HH], g_h2l[ROWS * HH];  // ln2 out

// ---------------- PTX helpers (sm_80+ baseline; no arch-specific ops) ------
__device__ __forceinline__ uint32_t smem_to_u32(const void* p) {
    uint32_t a;
    asm("{ .reg .u64 t; cvta.to.shared.u64 t, %1; cvt.u32.u64 %0, t; }"
        : "=r"(a) : "l"(p));
    return a;
}
__device__ __forceinline__ void ldmx4(uint32_t* r, uint32_t addr) {
    asm volatile("ldmatrix.sync.aligned.m8n8.x4.shared.b16 {%0,%1,%2,%3}, [%4];"
        : "=r"(r[0]), "=r"(r[1]), "=r"(r[2]), "=r"(r[3]) : "r"(addr));
}
__device__ __forceinline__ void mma16816(float* d, const uint32_t* a,
                                         uint32_t b0, uint32_t b1) {
    asm volatile("mma.sync.aligned.m16n8k16.row.col.f32.bf16.bf16.f32 "
        "{%0,%1,%2,%3}, {%4,%5,%6,%7}, {%8,%9}, {%0,%1,%2,%3};"
        : "+f"(d[0]), "+f"(d[1]), "+f"(d[2]), "+f"(d[3])
        : "r"(a[0]), "r"(a[1]), "r"(a[2]), "r"(a[3]), "r"(b0), "r"(b1));
}
#define CP16(dst, src) asm volatile( \
    "cp.async.ca.shared.global [%0], [%1], 16;" :: "r"(dst), "l"(src))
#define CP_COMMIT() asm volatile("cp.async.commit_group;")
#define CP_WAIT1() asm volatile("cp.async.wait_group 1;")
#define CP_WAIT0() asm volatile("cp.async.wait_group 0;")

// split helper: fp32 pair -> (hi bf16x2, lo bf16x2) packed
__device__ __forceinline__ void split2(float a0, float a1,
                                       __nv_bfloat162& h, __nv_bfloat162& l) {
    __nv_bfloat16 h0 = __float2bfloat16_rn(a0);
    __nv_bfloat16 h1 = __float2bfloat16_rn(a1);
    h.x = h0; h.y = h1;
    l.x = __float2bfloat16_rn(a0 - __bfloat162float(h0));
    l.y = __float2bfloat16_rn(a1 - __bfloat162float(h1));
}

// ---------------- HMMA GEMM with cp.async double buffering ------------------
// C[M,Nout] = A[M,K] @ Wt^T.  A, Wt both pre-split bf16, K-major.
// Block tile 128x128, BK=32; 8 warps, warp tile 32x64.
// D += Ahi*Bhi + Ahi*Blo + Alo*Bhi (fp32 accum).
#define LDP 40                      // bf16 row stride: 80B, ldmatrix conflict-free
#define TILE_B (128 * LDP * 2)      // 10240 B per tile
#define STAGE_B (4 * TILE_B)        // 40960 B per stage
#define SMEM_TOT (2 * STAGE_B)      // 81920 B

__global__ __launch_bounds__(256, 2) void mma_gemm(
    const __nv_bfloat16* __restrict__ Ahi, const __nv_bfloat16* __restrict__ Alo,
    const __nv_bfloat16* __restrict__ Bhi, const __nv_bfloat16* __restrict__ Blo,
    float* __restrict__ C, int K, int Nout,
    const float* __restrict__ colBias, const float* __restrict__ batchBias,
    int doRelu)
{
    extern __shared__ char smraw[];
    uint32_t sbase = smem_to_u32(smraw);
    int tid = threadIdx.x, lane = tid & 31, wid = tid >> 5;
    int wm = wid & 3, wn = wid >> 2;
    int bn = blockIdx.x, bm = blockIdx.y;

    float acc[2][8][4];
    #pragma unroll
    for (int i = 0; i < 2; i++)
        #pragma unroll
        for (int j = 0; j < 8; j++)
            #pragma unroll
            for (int q = 0; q < 4; q++) acc[i][j][q] = 0.f;

    // staging coords: 2 granules (16B) per tile per thread
    int sr = tid >> 2;              // row 0..63 (+64*it)... see below
    // per it: g = it*256+tid, row = g>>2 (0..127), k8 = (g&3)*8
    const int nch = K >> 5;

    #define ISSUE_CHUNK(c) do { \
        int k0 = (c) << 5; \
        uint32_t stb = sbase + ((c) & 1) * STAGE_B; \
        _Pragma("unroll") \
        for (int it = 0; it < 2; ++it) { \
            int g = it * 256 + tid; \
            int r = g >> 2, k8 = (g & 3) << 3; \
            uint32_t doff = stb + (uint32_t)(r * LDP + k8) * 2; \
            size_t ga = (size_t)(bm * 128 + r) * K + k0 + k8; \
            size_t gb = (size_t)(bn * 128 + r) * K + k0 + k8; \
            CP16(doff,              Ahi + ga); \
            CP16(doff + TILE_B,     Alo + ga); \
            CP16(doff + 2 * TILE_B, Bhi + gb); \
            CP16(doff + 3 * TILE_B, Blo + gb); \
        } \
        CP_COMMIT(); \
    } while (0)

    (void)sr;
    ISSUE_CHUNK(0);

    for (int c = 0; c < nch; ++c) {
        if (c + 1 < nch) { ISSUE_CHUNK(c + 1); CP_WAIT1(); }
        else            { CP_WAIT0(); }
        __syncthreads();

        uint32_t stb = sbase + (c & 1) * STAGE_B;
        #pragma unroll
        for (int ks = 0; ks < 2; ++ks) {
            uint32_t ah[2][4], al[2][4];
            #pragma unroll
            for (int mt = 0; mt < 2; ++mt) {
                uint32_t off = stb + (uint32_t)(((wm * 32 + mt * 16 + (lane & 15)) * LDP
                                                 + ks * 16 + (lane >> 4) * 8) * 2);
                ldmx4(ah[mt], off);
                ldmx4(al[mt], off + TILE_B);
            }
            #pragma unroll
            for (int ph = 0; ph < 2; ++ph) {
                uint32_t bh[2][4], bl[2][4];
                #pragma unroll
                for (int pp = 0; pp < 2; ++pp) {
                    int p = ph * 2 + pp;
                    uint32_t off = stb + 2 * TILE_B
                        + (uint32_t)(((wn * 64 + p * 16 + (lane & 7)
                                       + ((lane >> 4) << 3)) * LDP
                                      + ks * 16 + ((lane >> 3) & 1) * 8) * 2);
                    ldmx4(bh[pp], off);
                    ldmx4(bl[pp], off + TILE_B);
                }
                #pragma unroll
                for (int mt = 0; mt < 2; ++mt)
                    #pragma unroll
                    for (int pp = 0; pp < 2; ++pp) {
                        int nt = (ph * 2 + pp) * 2;
                        mma16816(acc[mt][nt],     ah[mt], bh[pp][0], bh[pp][1]);
                        mma16816(acc[mt][nt],     ah[mt], bl[pp][0], bl[pp][1]);
                        mma16816(acc[mt][nt],     al[mt], bh[pp][0], bh[pp][1]);
                        mma16816(acc[mt][nt + 1], ah[mt], bh[pp][2], bh[pp][3]);
                        mma16816(acc[mt][nt + 1], ah[mt], bl[pp][2], bl[pp][3]);
                        mma16816(acc[mt][nt + 1], al[mt], bh[pp][2], bh[pp][3]);
                    }
            }
        }
        __syncthreads();
    }

    // ---- epilogue ----
    #pragma unroll
    for (int mt = 0; mt < 2; ++mt) {
        #pragma unroll
        for (int half = 0; half < 2; ++half) {
            int row = bm * 128 + wm * 32 + mt * 16 + half * 8 + (lane >> 2);
            float* Cr = C + (size_t)row * Nout;
            const float* bbr = batchBias
                ? batchBias + (size_t)(row >> 11) * Nout : nullptr;
            #pragma unroll
            for (int nt = 0; nt < 8; ++nt) {
                int col = bn * 128 + wn * 64 + nt * 8 + 2 * (lane & 3);
                float x = acc[mt][nt][half * 2 + 0];
                float y = acc[mt][nt][half * 2 + 1];
                if (colBias) {
                    float2 cb = *(const float2*)(colBias + col);
                    x += cb.x; y += cb.y;
                }
                if (bbr) {
                    float2 bb = *(const float2*)(bbr + col);
                    x += bb.x; y += bb.y;
                }
                if (doRelu) { x = fmaxf(x, 0.f); y = fmaxf(y, 0.f); }
                *(float2*)(Cr + col) = make_float2(x, y);
            }
        }
    }
}

// ---------------- weight transpose + bf16 split (once per launch) -----------
__global__ void wsplit_kernel(const float* __restrict__ W, int K, int N,
                              __nv_bfloat16* __restrict__ hi,
                              __nv_bfloat16* __restrict__ lo) {
    int idx = blockIdx.x * 256 + threadIdx.x;   // = n*K + k
    if (idx >= N * K) return;
    int n = idx / K, k = idx - n * K;
    float v = W[(size_t)k * N + n];
    __nv_bfloat16 h = __float2bfloat16_rn(v);
    hi[idx] = h;
    lo[idx] = __float2bfloat16_rn(v - __bfloat162float(h));
}

// ---------------- graph / Laplacian build ----------------------------------

__global__ void init_graph_kernel(int* deg, int* rowcnt, int* fill) {
    int i = blockIdx.x * 256 + threadIdx.x;
    if (i < NN) { deg[i] = 1; rowcnt[i] = 0; fill[i] = 0; }
}

__global__ void edgew_kernel(const float* __restrict__ attr,
                             const float* __restrict__ w1, const float* __restrict__ b1,
                             const float* __restrict__ w2, const float* __restrict__ b2,
                             float* __restrict__ ew) {
    int e = blockIdx.x * 256 + threadIdx.x;
    if (e >= EE) return;
    float a = attr[e];
    float s = b2[0];
    #pragma unroll
    for (int j = 0; j < 32; j++) {
        float h = fmaxf(fmaf(a, w1[j], b1[j]), 0.f);
        s = fmaf(h, w2[j], s);
    }
    ew[e] = 1.f / (1.f + expf(-s));
}

__global__ void count_kernel(const int* __restrict__ ei, int* rowcnt, int* deg) {
    int e = blockIdx.x * 256 + threadIdx.x;
    if (e >= EE) return;
    atomicAdd(&rowcnt[ei[e]], 1);
    atomicAdd(&deg[ei[EE + e]], 1);
}

__global__ void disdiag_kernel(const int* __restrict__ deg, float* dis, float* diag) {
    int i = blockIdx.x * 256 + threadIdx.x;
    if (i >= NN) return;
    float d = rsqrtf((float)deg[i]);
    dis[i] = d;
    diag[i] = 1.f - d * d;
}

__global__ void scan_kernel(const int* __restrict__ cnt, int* __restrict__ rowptr) {
    __shared__ int part[256];
    int t = threadIdx.x;
    int loc[8]; int s = 0;
    #pragma unroll
    for (int i = 0; i < 8; i++) { loc[i] = s; s += cnt[t * 8 + i]; }
    part[t] = s;
    __syncthreads();
    for (int off = 1; off < 256; off <<= 1) {
        int v = (t >= off) ? part[t - off] : 0;
        __syncthreads();
        part[t] += v;
        __syncthreads();
    }
    int base = t ? part[t - 1] : 0;
    #pragma unroll
    for (int i = 0; i < 8; i++) rowptr[t * 8 + i] = base + loc[i];
    if (t == 255) rowptr[NN] = part[255];
}

__global__ void scatter_kernel(const int* __restrict__ ei, const float* __restrict__ ew,
                               const float* __restrict__ dis, const int* __restrict__ rowptr,
                               int* fill, int* __restrict__ colidx, float* __restrict__ val) {
    int e = blockIdx.x * 256 + threadIdx.x;
    if (e >= EE) return;
    int r = ei[e], c = ei[EE + e];
    int pos = rowptr[r] + atomicAdd(&fill[r], 1);
    colidx[pos] = c;
    val[pos] = dis[r] * ew[e] * dis[c];
}

// ---------------- context projection ----------------------------------------
__global__ void ctxproj_kernel(const float* __restrict__ context,
                               const float* __restrict__ w1, const float* __restrict__ b1,
                               float* __restrict__ out) {
    int b = blockIdx.x, n = threadIdx.x;
    float s = b1[n];
    for (int k = 0; k < FF; k++)
        s = fmaf(context[b * FF + k], w1[(size_t)(FF + k) * HH + n], s);
    out[b * HH + n] = s;
}

// ---------------- LayerNorm(512) + ReLU -> split bf16 hi/lo ----------------
__global__ __launch_bounds__(256) void ln_relu_split(
    const float* __restrict__ x, const float* __restrict__ g,
    const float* __restrict__ b,
    __nv_bfloat162* __restrict__ oh, __nv_bfloat162* __restrict__ ol)
{
    int row = blockIdx.x;
    const float* xr = x + (size_t)row * HH;
    int t = threadIdx.x;
    float2 v = ((const float2*)xr)[t];
    __shared__ float ws[8];
    __shared__ float mu_s, inv_s;
    int lane = t & 31, w = t >> 5;

    float s = v.x + v.y;
    #pragma unroll
    for (int o = 16; o; o >>= 1) s += __shfl_xor_sync(0xffffffffu, s, o);
    if (!lane) ws[w] = s;
    __syncthreads();
    if (t == 0) {
        float tot = 0.f;
        #pragma unroll
        for (int i = 0; i < 8; i++) tot += ws[i];
        mu_s = tot * (1.f / HH);
    }
    __syncthreads();
    float mu = mu_s;
    float dx = v.x - mu, dy = v.y - mu;
    s = dx * dx + dy * dy;
    #pragma unroll
    for (int o = 16; o; o >>= 1) s += __shfl_xor_sync(0xffffffffu, s, o);
    if (!lane) ws[w] = s;
    __syncthreads();
    if (t == 0) {
        float tot = 0.f;
        #pragma unroll
        for (int i = 0; i < 8; i++) tot += ws[i];
        inv_s = rsqrtf(tot * (1.f / HH) + 1e-5f);
    }
    __syncthreads();
    float inv = inv_s;
    float2 gv = ((const float2*)g)[t];
    float2 bv = ((const float2*)b)[t];
    float ox = fmaxf(fmaf(dx * inv, gv.x, bv.x), 0.f);
    float oy = fmaxf(fmaf(dy * inv, gv.y, bv.y), 0.f);
    __nv_bfloat162 h, l;
    split2(ox, oy, h, l);
    oh[(size_t)row * (HH / 2) + t] = h;
    ol[(size_t)row * (HH / 2) + t] = l;
}

// ---------------- dcoef: sigmoid(row-dot) ----------------------------------
__global__ __launch_bounds__(256) void dcoef_kernel(const float* __restrict__ g1,
                                                    const float* __restrict__ w2,
                                                    const float* __restrict__ b2,
                                                    float* __restrict__ dc) {
    int lane = threadIdx.x & 31, w = threadIdx.x >> 5;
    int row = blockIdx.x * 8 + w;
    const float* r = g1 + (size_t)row * FF;
    float s = 0.f;
    #pragma unroll
    for (int j = 0; j < FF / 32; j++)
        s = fmaf(r[lane + j * 32], w2[lane + j * 32], s);
    #pragma unroll
    for (int o = 16; o; o >>= 1) s += __shfl_xor_sync(0xffffffffu, s, o);
    if (!lane) dc[row] = 1.f / (1.f + expf(-(s + b2[0])));
}

// ---------------- fused SpMM diffusion + combine ----------------------------
__global__ __launch_bounds__(256) void spmm_kernel(
    const float* __restrict__ y, const float* __restrict__ temporal,
    const float* __restrict__ dc, const int* __restrict__ rowptr,
    const int* __restrict__ colidx, const float* __restrict__ val,
    const float* __restrict__ diag, float* __restrict__ kout)
{
    int i = blockIdx.x, b = blockIdx.y, f = threadIdx.x;
    const float* yb = y + (size_t)b * NN * FF;
    float acc = diag[i] * yb[(size_t)i * FF + f];
    int e1 = rowptr[i + 1];
    for (int e = rowptr[i]; e < e1; ++e)
        acc = fmaf(-val[e], yb[(size_t)colidx[e] * FF + f], acc);
    size_t o = ((size_t)b * NN + i) * FF + f;
    kout[o] = temporal[o] - dc[b * NN + i] * acc;
}

// ---------------- stage combine + split: out = y + sum c_j k_j --------------
__global__ __launch_bounds__(256) void axpy_split(
    float4* __restrict__ out, uint2* __restrict__ oh, uint2* __restrict__ ol,
    const float4* __restrict__ y,
    const float4* k0, const float4* k1, const float4* k2,
    const float4* k3, const float4* k4, const float4* k5,
    float c0, float c1, float c2, float c3, float c4, float c5)
{
    int i = blockIdx.x * 256 + threadIdx.x;
    float4 v = y[i];
#define ACCK(kk, cc) if (kk) { float4 a = kk[i]; \
    v.x = fmaf(cc, a.x, v.x); v.y = fmaf(cc, a.y, v.y); \
    v.z = fmaf(cc, a.z, v.z); v.w = fmaf(cc, a.w, v.w); }
    ACCK(k0, c0) ACCK(k1, c1) ACCK(k2, c2) ACCK(k3, c3) ACCK(k4, c4) ACCK(k5, c5)
#undef ACCK
    out[i] = v;
    union { __nv_bfloat162 b2[2]; uint2 u; } H, L;
    split2(v.x, v.y, H.b2[0], L.b2[0]);
    split2(v.z, v.w, H.b2[1], L.b2[1]);
    oh[i] = H.u;
    ol[i] = L.u;
}

__global__ void copy_split(float4* __restrict__ dst, uint2* __restrict__ oh,
                           uint2* __restrict__ ol, const float4* __restrict__ src) {
    int i = blockIdx.x * 256 + threadIdx.x;
    float4 v = src[i];
    dst[i] = v;
    union { __nv_bfloat162 b2[2]; uint2 u; } H, L;
    split2(v.x, v.y, H.b2[0], L.b2[0]);
    split2(v.z, v.w, H.b2[1], L.b2[1]);
    oh[i] = H.u;
    ol[i] = L.u;
}

// ---------------- host orchestration ----------------------------------------

struct Wts {
    const float *td_b2, *ln1_g, *ln1_b, *ln2_g, *ln2_b, *td_b3,
                *df_b1, *df_w2, *df_b2;
    float *h1, *h2, *tmp, *g1, *dc, *ctx;
    const int *rowptr, *colidx;
    const float *val, *diag;
    const __nv_bfloat16 *w1h, *w1l, *w2h, *w2l, *w3h, *w3l, *dfh, *dfl;
    const __nv_bfloat16 *ysh, *ysl;
    __nv_bfloat16 *h1h, *h1l, *h2h, *h2l;
};

static void feval(const float* y, float* kout, const Wts& w) {
    mma_gemm<<<dim3(4, 64), 256, SMEM_TOT>>>(w.ysh, w.ysl, w.w1h, w.w1l, w.h1,
                                             FF, HH, nullptr, w.ctx, 0);
    ln_relu_split<<<ROWS, 256>>>(w.h1, w.ln1_g, w.ln1_b,
                                 (__nv_bfloat162*)w.h1h, (__nv_bfloat162*)w.h1l);
    mma_gemm<<<dim3(4, 64), 256, SMEM_TOT>>>(w.h1h, w.h1l, w.w2h, w.w2l, w.h2,
                                             HH, HH, w.td_b2, nullptr, 0);
    ln_relu_split<<<ROWS, 256>>>(w.h2, w.ln2_g, w.ln2_b,
                                 (__nv_bfloat162*)w.h2h, (__nv_bfloat162*)w.h2l);
    mma_gemm<<<dim3(2, 64), 256, SMEM_TOT>>>(w.h2h, w.h2l, w.w3h, w.w3l, w.tmp,
                                             HH, FF, w.td_b3, nullptr, 0);
    mma_gemm<<<dim3(2, 64), 256, SMEM_TOT>>>(w.ysh, w.ysl, w.dfh, w.dfl, w.g1,
                                             FF, FF, w.df_b1, nullptr, 1);
    dcoef_kernel<<<ROWS / 8, 256>>>(w.g1, w.df_w2, w.df_b2, w.dc);
    spmm_kernel<<<dim3(NN, BB), 256>>>(y, w.tmp, w.dc, w.rowptr, w.colidx,
                                       w.val, w.diag, kout);
}

extern "C" void kernel_launch(void* const* d_in, const int* in_sizes, int n_in,
                              void* d_out, int out_size)
{
    const float* state     = (const float*)d_in[0];
    const float* context   = (const float*)d_in[1];
    const float* edge_attr = (const float*)d_in[2];
    const int*   edge_idx  = (const int*)  d_in[3];
    const float* ew_w1 = (const float*)d_in[4];
    const float* ew_b1 = (const float*)d_in[5];
    const float* ew_w2 = (const float*)d_in[6];
    const float* ew_b2 = (const float*)d_in[7];
    const float* td_w1 = (const float*)d_in[8];
    const float* td_b1 = (const float*)d_in[9];
    const float* ln1_g = (const float*)d_in[10];
    const float* ln1_b = (const float*)d_in[11];
    const float* td_w2 = (const float*)d_in[12];
    const float* td_b2 = (const float*)d_in[13];
    const float* ln2_g = (const float*)d_in[14];
    const float* ln2_b = (const float*)d_in[15];
    const float* td_w3 = (const float*)d_in[16];
    const float* td_b3 = (const float*)d_in[17];
    const float* df_w1 = (const float*)d_in[18];
    const float* df_b1 = (const float*)d_in[19];
    const float* df_w2 = (const float*)d_in[20];
    const float* df_b2 = (const float*)d_in[21];

    float *kbuf, *ya, *yb, *yi, *h1, *h2, *tmp, *g1, *dc, *ctx;
    float *ew, *val, *dis, *diag;
    int *deg, *rowcnt, *fill, *rowptr, *colidx;
    __nv_bfloat16 *w1h, *w1l, *w2h, *w2l, *w3h, *w3l, *dfh, *dfl;
    __nv_bfloat16 *ysh, *ysl, *h1h, *h1l, *h2h, *h2l;
    cudaGetSymbolAddress((void**)&kbuf,  g_kbuf);
    cudaGetSymbolAddress((void**)&ya,    g_ya);
    cudaGetSymbolAddress((void**)&yb,    g_yb);
    cudaGetSymbolAddress((void**)&yi,    g_yi);
    cudaGetSymbolAddress((void**)&h1,    g_h1);
    cudaGetSymbolAddress((void**)&h2,    g_h2);
    cudaGetSymbolAddress((void**)&tmp,   g_tmp);
    cudaGetSymbolAddress((void**)&g1,    g_g1);
    cudaGetSymbolAddress((void**)&dc,    g_dc);
    cudaGetSymbolAddress((void**)&ctx,   g_ctx);
    cudaGetSymbolAddress((void**)&ew,    g_ew);
    cudaGetSymbolAddress((void**)&val,   g_val);
    cudaGetSymbolAddress((void**)&dis,   g_dis);
    cudaGetSymbolAddress((void**)&diag,  g_diag);
    cudaGetSymbolAddress((void**)&deg,   g_deg);
    cudaGetSymbolAddress((void**)&rowcnt,g_rowcnt);
    cudaGetSymbolAddress((void**)&fill,  g_fill);
    cudaGetSymbolAddress((void**)&rowptr,g_rowptr);
    cudaGetSymbolAddress((void**)&colidx,g_colidx);
    cudaGetSymbolAddress((void**)&w1h, g_w1t_h);
    cudaGetSymbolAddress((void**)&w1l, g_w1t_l);
    cudaGetSymbolAddress((void**)&w2h, g_w2t_h);
    cudaGetSymbolAddress((void**)&w2l, g_w2t_l);
    cudaGetSymbolAddress((void**)&w3h, g_w3t_h);
    cudaGetSymbolAddress((void**)&w3l, g_w3t_l);
    cudaGetSymbolAddress((void**)&dfh, g_dft_h);
    cudaGetSymbolAddress((void**)&dfl, g_dft_l);
    cudaGetSymbolAddress((void**)&ysh, g_ysh);
    cudaGetSymbolAddress((void**)&ysl, g_ysl);
    cudaGetSymbolAddress((void**)&h1h, g_h1h);
    cudaGetSymbolAddress((void**)&h1l, g_h1l);
    cudaGetSymbolAddress((void**)&h2h, g_h2h);
    cudaGetSymbolAddress((void**)&h2l, g_h2l);

    cudaFuncSetAttribute(mma_gemm, cudaFuncAttributeMaxDynamicSharedMemorySize,
                         SMEM_TOT);

    // ---- 1. Build normalized Laplacian as CSR ----
    init_graph_kernel<<<NN / 256, 256>>>(deg, rowcnt, fill);
    edgew_kernel<<<EE / 256, 256>>>(edge_attr, ew_w1, ew_b1, ew_w2, ew_b2, ew);
    count_kernel<<<EE / 256, 256>>>(edge_idx, rowcnt, deg);
    disdiag_kernel<<<NN / 256, 256>>>(deg, dis, diag);
    scan_kernel<<<1, 256>>>(rowcnt, rowptr);
    scatter_kernel<<<EE / 256, 256>>>(edge_idx, ew, dis, rowptr, fill, colidx, val);

    // ---- 2. Constant context projection + weight transpose/split ----
    ctxproj_kernel<<<BB, HH>>>(context, td_w1, td_b1, ctx);
    wsplit_kernel<<<(HH * FF + 255) / 256, 256>>>(td_w1, FF, HH, w1h, w1l);
    wsplit_kernel<<<(HH * HH + 255) / 256, 256>>>(td_w2, HH, HH, w2h, w2l);
    wsplit_kernel<<<(FF * HH + 255) / 256, 256>>>(td_w3, HH, FF, w3h, w3l);
    wsplit_kernel<<<(FF * FF + 255) / 256, 256>>>(df_w1, FF, FF, dfh, dfl);

    // ---- 3. y0 = state (+ split) ----
    copy_split<<<TOT / 4 / 256, 256>>>((float4*)ya, (uint2*)ysh, (uint2*)ysl,
                                       (const float4*)state);

    Wts w;
    w.td_b2 = td_b2; w.ln1_g = ln1_g; w.ln1_b = ln1_b;
    w.ln2_g = ln2_g; w.ln2_b = ln2_b; w.td_b3 = td_b3;
    w.df_b1 = df_b1; w.df_w2 = df_w2; w.df_b2 = df_b2;
    w.h1 = h1; w.h2 = h2; w.tmp = tmp; w.g1 = g1; w.dc = dc; w.ctx = ctx;
    w.rowptr = rowptr; w.colidx = colidx; w.val = val; w.diag = diag;
    w.w1h = w1h; w.w1l = w1l; w.w2h = w2h; w.w2l = w2l;
    w.w3h = w3h; w.w3l = w3l; w.dfh = dfh; w.dfl = dfl;
    w.ysh = ysh; w.ysl = ysl;
    w.h1h = h1h; w.h1l = h1l; w.h2h = h2h; w.h2l = h2l;

    // ---- 4. dopri5, 4 fixed steps, FSAL reuse ----
    const double dt = 0.25;
    const double A2[1] = {1.0 / 5};
    const double A3[2] = {3.0 / 40, 9.0 / 40};
    const double A4[3] = {44.0 / 45, -56.0 / 15, 32.0 / 9};
    const double A5[4] = {19372.0 / 6561, -25360.0 / 2187, 64448.0 / 6561, -212.0 / 729};
    const double A6[5] = {9017.0 / 3168, -355.0 / 33, 46732.0 / 5247, 49.0 / 176, -5103.0 / 18656};
    const double BW[6] = {35.0 / 384, 0.0, 500.0 / 1113, 125.0 / 192, -2187.0 / 6784, 11.0 / 84};
    const double* Arows[5] = {A2, A3, A4, A5, A6};

    float* kp[7];
    for (int i = 0; i < 7; i++) kp[i] = kbuf + (size_t)i * TOT;

    float* ycur = ya;
    float* yoth = yb;
    const int nAx = TOT / 4 / 256;

    for (int s = 0; s < 4; ++s) {
        if (s == 0) feval(ycur, kp[0], w);   // else FSAL: kp[0] = prev step's k7

        for (int i = 1; i <= 5; ++i) {
            const double* a = Arows[i - 1];
            const float4* ks[6] = {nullptr, nullptr, nullptr, nullptr, nullptr, nullptr};
            float cs[6] = {0, 0, 0, 0, 0, 0};
            for (int j = 0; j < i; j++) { ks[j] = (const float4*)kp[j]; cs[j] = (float)(dt * a[j]); }
            axpy_split<<<nAx, 256>>>((float4*)yi, (uint2*)ysh, (uint2*)ysl,
                                     (const float4*)ycur,
                                     ks[0], ks[1], ks[2], ks[3], ks[4], ks[5],
                                     cs[0], cs[1], cs[2], cs[3], cs[4], cs[5]);
            feval(yi, kp[i], w);
        }

        float* ynext = (s == 3) ? (float*)d_out : yoth;
        axpy_split<<<nAx, 256>>>((float4*)ynext, (uint2*)ysh, (uint2*)ysl,
                                 (const float4*)ycur,
                                 (const float4*)kp[0], nullptr,
                                 (const float4*)kp[2], (const float4*)kp[3],
                                 (const float4*)kp[4], (const float4*)kp[5],
                                 (float)(dt * BW[0]), 0.f,
                                 (float)(dt * BW[2]), (float)(dt * BW[3]),
                                 (float)(dt * BW[4]), (float)(dt * BW[5]));

        if (s < 3) {
            feval(ynext, kp[6], w);
            float* t = kp[0]; kp[0] = kp[6]; kp[6] = t;
            yoth = ycur;
            ycur = ynext;
        }
    }
}